// round 7
// baseline (speedup 1.0000x reference)
#include <cuda_runtime.h>
#include <math.h>
#include <float.h>

#define BB 4
#define NP0 4096
#define NEWP 1152
#define MAXN (NP0 + 10*NEWP)     // 15616
#define GD 256
#define HD 128
#define KSEL 64
#define NSTEPS 10
#define REFO (NEWP*3)            // 3456

// ---------------- device scratch (static: no allocation) ----------------
__device__ float    g_canvas[BB][MAXN][3];
__device__ float    g_F2T[128][BB*MAXN];      // encoder layer-2 activations, transposed
__device__ unsigned g_gfenc[BB][GD];
__device__ float    g_h[BB][HD];
__device__ float    g_c[BB][HD];
__device__ float    g_scores[BB][MAXN];
__device__ float    g_center[BB][3];
__device__ float    g_patch[BB][3];
__device__ float    g_attbias[BB][128];
__device__ unsigned g_syncctr[BB];
__device__ double   g_acc[4];

// monotone float<->uint encoding (for atomicMax over signed floats)
__device__ __forceinline__ unsigned fenc(float f){
    unsigned u = __float_as_uint(f);
    return (u & 0x80000000u) ? ~u : (u | 0x80000000u);
}
__device__ __forceinline__ float fdec(unsigned e){
    unsigned u = (e & 0x80000000u) ? (e & 0x7fffffffu) : ~e;
    return __uint_as_float(u);
}

// ---------------- init ----------------
__global__ void k_init(const float* __restrict__ points){
    int i = blockIdx.x*blockDim.x + threadIdx.x;
    if(i < BB*NP0*3){
        int b = i/(NP0*3); int r = i - b*(NP0*3);
        g_canvas[b][r/3][r%3] = points[i];
    }
    if(i < BB*HD){ g_h[i/HD][i%HD] = 0.f; g_c[i/HD][i%HD] = 0.f; }
    if(i < 4){ g_acc[i] = 0.0; g_syncctr[i] = 0u; }
}

// ---------------- encoder layers 1-2 (per point), fused gfeat re-init ----------------
__global__ void k_enc12(const float* __restrict__ w1, const float* __restrict__ b1,
                        const float* __restrict__ w2, const float* __restrict__ b2, int N){
    __shared__ float s_w1[192];
    __shared__ float s_b1[64];
    __shared__ float s_w2[64*128];
    __shared__ float s_b2[128];
    int tid = threadIdx.x;
    if(blockIdx.x == 0){  // re-init gfeat max accumulators for this step
        for(int i=tid;i<BB*GD;i+=256) ((unsigned*)g_gfenc)[i] = fenc(-FLT_MAX);
    }
    for(int i=tid;i<192;i+=256) s_w1[i]=w1[i];
    if(tid<64)  s_b1[tid]=b1[tid];
    if(tid<128) s_b2[tid]=b2[tid];
    for(int i=tid;i<8192;i+=256) s_w2[i]=w2[i];
    __syncthreads();

    int p = blockIdx.x*256 + tid;
    if(p >= BB*N) return;
    int b = p / N, n = p - b*N;
    float x = g_canvas[b][n][0], y = g_canvas[b][n][1], z = g_canvas[b][n][2];

    float f1[64];
    #pragma unroll
    for(int o=0;o<64;o++)
        f1[o] = fmaxf(0.f, s_b1[o] + x*s_w1[o] + y*s_w1[64+o] + z*s_w1[128+o]);

    size_t col = (size_t)b*MAXN + n;
    for(int j=0;j<128;j+=4){
        float a0=s_b2[j], a1=s_b2[j+1], a2=s_b2[j+2], a3=s_b2[j+3];
        #pragma unroll
        for(int k=0;k<64;k++){
            float4 w = *(const float4*)&s_w2[k*128 + j];
            float f = f1[k];
            a0 += f*w.x; a1 += f*w.y; a2 += f*w.z; a3 += f*w.w;
        }
        g_F2T[j  ][col] = fmaxf(a0,0.f);
        g_F2T[j+1][col] = fmaxf(a1,0.f);
        g_F2T[j+2][col] = fmaxf(a2,0.f);
        g_F2T[j+3][col] = fmaxf(a3,0.f);
    }
}

// ---------------- encoder layer 3 GEMM + channel max + (last block) attention bias ----
// grid (BB, N/64), block 256.  Tile: 64 points x 256 channels.
// K=128 staged through smem in 4 chunks of 32 -> inner loop is pure LDS+FFMA.
// The last block per batch (ticket) computes the attention bias from final gfeat.
__global__ void __launch_bounds__(256,2)
k_enc3(const float* __restrict__ w3, const float* __restrict__ b3,
       const float* __restrict__ att_w1, const float* __restrict__ att_b1){
    __shared__ float sW[32*256];   // [kk][ch]  32KB
    __shared__ float sF[32*64];    // [kk][p]    8KB  (reused as reduce buf)
    __shared__ unsigned s_ticket;
    int b = blockIdx.x;
    int pbase = blockIdx.y*64;
    int tid = threadIdx.x;
    int lane = tid & 31, pg = tid >> 5;
    int c0 = lane*4, c1 = 128 + lane*4;
    size_t base = (size_t)b*MAXN + pbase;

    float acc[8][8];
    #pragma unroll
    for(int i=0;i<8;i++)
        #pragma unroll
        for(int j=0;j<8;j++) acc[i][j]=0.f;

    for(int kc=0;kc<128;kc+=32){
        __syncthreads();
        {   // stage w3 chunk: rows kc..kc+31 (contiguous 8192 floats)
            const float4* wsrc = (const float4*)(w3 + (size_t)kc*256);
            float4* wdst = (float4*)sW;
            #pragma unroll
            for(int i=0;i<8;i++) wdst[tid + i*256] = wsrc[tid + i*256];
        }
        {   // stage F2T chunk: 32 rows x 64 points
            #pragma unroll
            for(int i=0;i<8;i++){
                int idx = tid + i*256;
                int k = idx>>6, p = idx&63;
                sF[idx] = g_F2T[kc+k][base+p];
            }
        }
        __syncthreads();
        #pragma unroll 4
        for(int k=0;k<32;k++){
            float4 wa = *(const float4*)&sW[k*256 + c0];
            float4 wb = *(const float4*)&sW[k*256 + c1];
            float4 fa = *(const float4*)&sF[k*64 + pg*8];
            float4 fb = *(const float4*)&sF[k*64 + pg*8 + 4];
            float f[8] = {fa.x,fa.y,fa.z,fa.w,fb.x,fb.y,fb.z,fb.w};
            float w[8] = {wa.x,wa.y,wa.z,wa.w,wb.x,wb.y,wb.z,wb.w};
            #pragma unroll
            for(int i=0;i<8;i++)
                #pragma unroll
                for(int j=0;j<8;j++)
                    acc[i][j] += f[i]*w[j];
        }
    }
    // per-thread max over 8 points; +bias (max(a)+b == max(a+b))
    float m[8];
    #pragma unroll
    for(int j=0;j<8;j++){
        float mm = acc[0][j];
        #pragma unroll
        for(int i=1;i<8;i++) mm = fmaxf(mm, acc[i][j]);
        int ch = (j<4) ? (c0+j) : (c1+j-4);
        m[j] = mm + b3[ch];
    }
    __syncthreads();
    #pragma unroll
    for(int j=0;j<8;j++){
        int ch = (j<4) ? (c0+j) : (c1+j-4);
        sF[pg*256 + ch] = m[j];
    }
    __syncthreads();
    {
        int ch = tid;   // 256 channels
        float mm = sF[ch];
        #pragma unroll
        for(int g=1;g<8;g++) mm = fmaxf(mm, sF[g*256 + ch]);
        atomicMax(&g_gfenc[b][ch], fenc(mm));
    }
    // ----- ticket: last block of this batch computes attention bias -----
    __threadfence();
    __syncthreads();
    if(tid==0) s_ticket = atomicAdd(&g_syncctr[b], 1u);
    __syncthreads();
    if(s_ticket == gridDim.y - 1){
        __threadfence();
        int j = tid & 127, half = tid >> 7;   // 2 halves of the 384 rows
        float a = (half==0) ? att_b1[j] : 0.f;
        int r0 = half*192;
        #pragma unroll 4
        for(int rr=0;rr<192;rr++){
            int r = r0 + rr;
            float v = (r < GD) ? fdec(g_gfenc[b][r]) : g_h[b][r-GD];
            a += v * att_w1[(3+r)*128 + j];
        }
        sF[half*128 + j] = a;
        __syncthreads();
        if(tid < 128) g_attbias[b][tid] = sF[tid] + sF[128+tid];
        if(tid == 0) g_syncctr[b] = 0u;   // reset for next step (stream-ordered)
    }
}

// ---------------- attention score: 2 points per thread ----------------
// grid ((N+511)/512, BB), block 256.
__global__ void k_attscore(const float* __restrict__ att_w1, const float* __restrict__ att_w2,
                           const float* __restrict__ att_b2, int N){
    __shared__ float  s_ab[128];
    __shared__ float4 s_pk[128];       // {w1x,w1y,w1z,w2} per hidden unit
    int b = blockIdx.y;
    int tid = threadIdx.x;
    if(tid < 128){
        s_ab[tid] = g_attbias[b][tid];
        s_pk[tid] = make_float4(att_w1[tid], att_w1[128+tid], att_w1[256+tid], att_w2[tid]);
    }
    __syncthreads();

    int n0 = blockIdx.x*512 + tid;
    int n1 = n0 + 256;
    bool a0 = n0 < N, a1 = n1 < N;
    float x0=0,y0=0,z0=0,x1=0,y1=0,z1=0;
    if(a0){ x0=g_canvas[b][n0][0]; y0=g_canvas[b][n0][1]; z0=g_canvas[b][n0][2]; }
    if(a1){ x1=g_canvas[b][n1][0]; y1=g_canvas[b][n1][1]; z1=g_canvas[b][n1][2]; }
    float s0 = att_b2[0], s1 = att_b2[0];
    #pragma unroll 4
    for(int jj=0;jj<128;jj++){
        float4 w = s_pk[jj];
        float ab = s_ab[jj];
        float h0 = ab + x0*w.x + y0*w.y + z0*w.z;
        float h1 = ab + x1*w.x + y1*w.y + z1*w.z;
        s0 += fmaxf(h0, 0.f) * w.w;
        s1 += fmaxf(h1, 0.f) * w.w;
    }
    if(a0) g_scores[b][n0] = s0;
    if(a1) g_scores[b][n1] = s1;
}

// ---------------- fused softmax + center + top-K + LSTM + ref1 + ref2 ----------------
// one block per batch, 1024 threads, dynamic smem = MAXN*4 bytes for d2
__global__ void __launch_bounds__(1024)
k_center(int N,
         const float* __restrict__ wih, const float* __restrict__ whh,
         const float* __restrict__ bih, const float* __restrict__ bhh,
         const float* __restrict__ ref_w1, const float* __restrict__ ref_b1,
         const float* __restrict__ ref_w2, const float* __restrict__ ref_b2){
    extern __shared__ float sD[];
    __shared__ float rw[32];
    __shared__ int   ri[32];
    __shared__ float s4[32][4];
    __shared__ float s_bc[8];
    __shared__ int   s_cnt[2];
    __shared__ unsigned s_eqn;
    __shared__ int   s_eqi[256];
    __shared__ float s_in[262];
    __shared__ float s_gp[2][512];
    __shared__ float s_hold[HD];
    __shared__ float s_hid[HD];
    int b = blockIdx.x, tid = threadIdx.x;
    int lane = tid & 31, wid = tid >> 5;

    // --- max of scores ---
    float m = -FLT_MAX;
    for(int n=tid;n<N;n+=1024) m = fmaxf(m, g_scores[b][n]);
    #pragma unroll
    for(int o=16;o;o>>=1) m = fmaxf(m, __shfl_xor_sync(0xffffffffu, m, o));
    if(lane==0) rw[wid] = m;
    __syncthreads();
    if(tid==0){
        float mm = rw[0];
        for(int i=1;i<32;i++) mm = fmaxf(mm, rw[i]);
        s_bc[0] = mm;
        s_cnt[0] = 0; s_cnt[1] = 0;
        s_eqn = 0;
    }
    __syncthreads();
    float mx = s_bc[0];

    // --- exp sums + weighted coordinate sums ---
    float se=0,sx=0,sy=0,sz=0;
    for(int n=tid;n<N;n+=1024){
        float e = expf(g_scores[b][n]-mx);
        se += e;
        sx += e*g_canvas[b][n][0];
        sy += e*g_canvas[b][n][1];
        sz += e*g_canvas[b][n][2];
    }
    #pragma unroll
    for(int o=16;o;o>>=1){
        se += __shfl_xor_sync(0xffffffffu, se, o);
        sx += __shfl_xor_sync(0xffffffffu, sx, o);
        sy += __shfl_xor_sync(0xffffffffu, sy, o);
        sz += __shfl_xor_sync(0xffffffffu, sz, o);
    }
    if(lane==0){ s4[wid][0]=se; s4[wid][1]=sx; s4[wid][2]=sy; s4[wid][3]=sz; }
    __syncthreads();
    if(tid==0){
        float te=0,tx=0,ty=0,tz=0;
        for(int i=0;i<32;i++){ te+=s4[i][0]; tx+=s4[i][1]; ty+=s4[i][2]; tz+=s4[i][3]; }
        float cx=tx/te, cy=ty/te, cz=tz/te;
        s_bc[1]=cx; s_bc[2]=cy; s_bc[3]=cz;
        g_center[b][0]=cx; g_center[b][1]=cy; g_center[b][2]=cz;
    }
    __syncthreads();
    float cx=s_bc[1], cy=s_bc[2], cz=s_bc[3];

    // --- squared distances into smem (monotone with dist -> same top-K) ---
    for(int n=tid;n<N;n+=1024){
        float dx=g_canvas[b][n][0]-cx, dy=g_canvas[b][n][1]-cy, dz=g_canvas[b][n][2]-cz;
        sD[n] = dx*dx+dy*dy+dz*dz;
    }
    __syncthreads();

    // --- binary search on (nonneg) float bits for K-th smallest ---
    // one sync per iteration: parity-indexed counters, reset the other one
    unsigned lo=0u, hi=0x7f800000u;
    int it = 0;
    while(lo < hi){
        unsigned mid = lo + ((hi-lo)>>1);
        int c=0;
        for(int n=tid;n<N;n+=1024) c += (__float_as_uint(sD[n]) <= mid);
        #pragma unroll
        for(int o=16;o;o>>=1) c += __shfl_xor_sync(0xffffffffu, c, o);
        int p = it & 1;
        if(lane==0) atomicAdd(&s_cnt[p], c);
        if(tid==0) s_cnt[p^1] = 0;
        __syncthreads();
        if(s_cnt[p] >= KSEL) hi = mid; else lo = mid+1;
        it++;
    }
    unsigned u = lo;

    // --- sums of strictly-below + boundary ties (index order matches lax.top_k) ---
    float ax=0,ay=0,az=0; int c=0;
    for(int n=tid;n<N;n+=1024){
        unsigned bits = __float_as_uint(sD[n]);
        if(bits < u){
            c++; ax+=g_canvas[b][n][0]; ay+=g_canvas[b][n][1]; az+=g_canvas[b][n][2];
        }
        if(bits == u){
            unsigned p = atomicAdd(&s_eqn, 1u);
            if(p < 256) s_eqi[p] = n;
        }
    }
    #pragma unroll
    for(int o=16;o;o>>=1){
        c  += __shfl_xor_sync(0xffffffffu, c, o);
        ax += __shfl_xor_sync(0xffffffffu, ax, o);
        ay += __shfl_xor_sync(0xffffffffu, ay, o);
        az += __shfl_xor_sync(0xffffffffu, az, o);
    }
    if(lane==0){ ri[wid]=c; s4[wid][0]=ax; s4[wid][1]=ay; s4[wid][2]=az; }
    __syncthreads();
    if(tid==0){
        int tc=0; float tx=0,ty=0,tz=0;
        for(int i=0;i<32;i++){ tc+=ri[i]; tx+=s4[i][0]; ty+=s4[i][1]; tz+=s4[i][2]; }
        int r = KSEL - tc;                 // boundary elems needed, in index order
        int mcount = min((int)s_eqn, 256);
        for(int itx=0; itx<r; itx++){
            int best=-1, bi=0x7fffffff;
            for(int q=0;q<mcount;q++){ int v=s_eqi[q]; if(v>=0 && v<bi){bi=v;best=q;} }
            if(best<0) break;
            s_eqi[best] = -1;
            tx += g_canvas[b][bi][0]; ty += g_canvas[b][bi][1]; tz += g_canvas[b][bi][2];
        }
        float inv = 1.f/KSEL;
        float px = tx*inv - cx, py = ty*inv - cy, pz = tz*inv - cz;
        g_patch[b][0]=px; g_patch[b][1]=py; g_patch[b][2]=pz;
        s_bc[4]=px; s_bc[5]=py; s_bc[6]=pz;
    }
    __syncthreads();

    // ===== fused LSTM gates + cell + refine (this batch only) =====
    for(int i=tid;i<262;i+=1024){
        float v;
        if(i < GD)        v = fdec(g_gfenc[b][i]);
        else if(i < GD+3) v = s_bc[1+i-GD];
        else              v = s_bc[4+i-GD-3];
        s_in[i]=v;
    }
    for(int i=tid;i<HD;i+=1024) s_hold[i]=g_h[b][i];
    __syncthreads();
    {   // gates split 2-way over k: part0 = bias + in[0:131) + h[0:64); part1 = rest
        int j = tid & 511, part = tid >> 9;
        float a;
        if(part == 0){
            a = bih[j] + bhh[j];
            #pragma unroll 2
            for(int k=0;k<131;k++) a += s_in[k]*wih[k*512 + j];
            #pragma unroll 2
            for(int k=0;k<64;k++)  a += s_hold[k]*whh[k*512 + j];
        } else {
            a = 0.f;
            #pragma unroll 2
            for(int k=131;k<262;k++) a += s_in[k]*wih[k*512 + j];
            #pragma unroll 2
            for(int k=64;k<128;k++)  a += s_hold[k]*whh[k*512 + j];
        }
        s_gp[part][j] = a;
    }
    __syncthreads();
    if(tid < HD){
        int j = tid;
        float gi=s_gp[0][j]      + s_gp[1][j];
        float gf=s_gp[0][HD+j]   + s_gp[1][HD+j];
        float gg=s_gp[0][2*HD+j] + s_gp[1][2*HD+j];
        float go=s_gp[0][3*HD+j] + s_gp[1][3*HD+j];
        float sgi=1.f/(1.f+expf(-gi)), sgf=1.f/(1.f+expf(-gf)), sgo=1.f/(1.f+expf(-go));
        float cc = sgf*g_c[b][j] + sgi*tanhf(gg);
        g_c[b][j] = cc;
        float h = sgo*tanhf(cc);
        g_h[b][j] = h;
    }
    __syncthreads();
    if(tid < HD){   // refine layer 1 (reads h via g_h-equivalent smem path)
        int j = tid;
        float a = ref_b1[j];
        #pragma unroll 2
        for(int k=0;k<HD;k++) a += g_h[b][k]*ref_w1[k*128+j];
        s_hid[j] = fmaxf(a, 0.f);
    }
    __syncthreads();
    {   // refine layer 2 -> new canvas points
        for(int q=tid; q<REFO; q+=1024){
            float a = ref_b2[q];
            #pragma unroll 4
            for(int k=0;k<HD;k++) a += s_hid[k]*ref_w2[k*REFO + q];
            int pt = q/3, d = q - 3*pt;
            g_canvas[b][N+pt][d] = a*0.02f + s_bc[1+d];
        }
    }
}

// ---------------- chamfer: all 4 directions in one launch ----------------
#define CTI 2048
__global__ void k_cham(const float* __restrict__ gt){
    __shared__ float4 sy[CTI];
    __shared__ float red[256];
    int b = blockIdx.y, tid = threadIdx.x;
    int t = blockIdx.x;
    int dir, tb;
    if(t < 16){ dir=0; tb=t; }
    else if(t < 32){ dir=1; tb=t-16; }
    else if(t < 77){ dir=2; tb=t-32; }
    else { dir=3; tb=t-77; }

    int xsel = (dir==1 || dir==3) ? 1 : 0;           // 0=canvas, 1=gt
    int xoff = (dir==2) ? NP0 : 0;
    int ysel = 1 - xsel;
    int yoff = (dir==3) ? NP0 : 0;
    int Ny   = (dir==3) ? (MAXN-NP0) : NP0;
    int ai   = dir;

    int n = tb*256 + tid;   // all tiles are full
    float x0,x1,x2;
    if(xsel==0){
        x0=g_canvas[b][xoff+n][0]; x1=g_canvas[b][xoff+n][1]; x2=g_canvas[b][xoff+n][2];
    } else {
        const float* p = gt + ((size_t)b*NP0 + n)*3;
        x0=p[0]; x1=p[1]; x2=p[2];
    }
    float xx = x0*x0 + x1*x1 + x2*x2;
    float mn0=FLT_MAX, mn1=FLT_MAX, mn2=FLT_MAX, mn3=FLT_MAX;

    for(int t0=0;t0<Ny;t0+=CTI){
        int cnt = min(CTI, Ny-t0);
        __syncthreads();
        if(ysel==0){
            for(int i=tid;i<cnt;i+=256){
                float y0=g_canvas[b][yoff+t0+i][0], y1=g_canvas[b][yoff+t0+i][1], y2=g_canvas[b][yoff+t0+i][2];
                sy[i] = make_float4(y0,y1,y2, y0*y0+y1*y1+y2*y2);
            }
        } else {
            const float* ys = gt + ((size_t)b*NP0 + t0)*3;
            for(int i=tid;i<cnt;i+=256){
                float y0=ys[3*i], y1=ys[3*i+1], y2=ys[3*i+2];
                sy[i] = make_float4(y0,y1,y2, y0*y0+y1*y1+y2*y2);
            }
        }
        __syncthreads();
        for(int j=0;j<cnt;j+=4){
            float4 A=sy[j], B=sy[j+1], C=sy[j+2], D=sy[j+3];
            float v0 = fmaf(-2.f, fmaf(x0,A.x, fmaf(x1,A.y, x2*A.z)), A.w);
            float v1 = fmaf(-2.f, fmaf(x0,B.x, fmaf(x1,B.y, x2*B.z)), B.w);
            float v2 = fmaf(-2.f, fmaf(x0,C.x, fmaf(x1,C.y, x2*C.z)), C.w);
            float v3 = fmaf(-2.f, fmaf(x0,D.x, fmaf(x1,D.y, x2*D.z)), D.w);
            mn0 = fminf(mn0, v0);
            mn1 = fminf(mn1, v1);
            mn2 = fminf(mn2, v2);
            mn3 = fminf(mn3, v3);
        }
    }
    float mn = fminf(fminf(mn0,mn1), fminf(mn2,mn3));
    red[tid] = xx + mn;
    __syncthreads();
    for(int s=128;s>0;s>>=1){ if(tid<s) red[tid]+=red[tid+s]; __syncthreads(); }
    if(tid==0) atomicAdd(&g_acc[ai], (double)red[0]);
}

__global__ void k_final(float* __restrict__ out){
    double cd_in  = g_acc[0]/(4.0*NP0)          + g_acc[1]/(4.0*NP0);
    double cd_new = g_acc[2]/(4.0*(10.0*NEWP))  + g_acc[3]/(4.0*NP0);
    out[0] = (float)(0.1*cd_in + 1.0*cd_new);
}

// ---------------- host launch ----------------
extern "C" void kernel_launch(void* const* d_in, const int* in_sizes, int n_in,
                              void* d_out, int out_size){
    const float* points   = (const float*)d_in[0];
    const float* gt       = (const float*)d_in[1];
    const float* enc_w1   = (const float*)d_in[2];
    const float* enc_b1   = (const float*)d_in[3];
    const float* enc_w2   = (const float*)d_in[4];
    const float* enc_b2   = (const float*)d_in[5];
    const float* enc_w3   = (const float*)d_in[6];
    const float* enc_b3   = (const float*)d_in[7];
    const float* att_w1   = (const float*)d_in[8];
    const float* att_b1   = (const float*)d_in[9];
    const float* att_w2   = (const float*)d_in[10];
    const float* att_b2   = (const float*)d_in[11];
    const float* lstm_wih = (const float*)d_in[12];
    const float* lstm_whh = (const float*)d_in[13];
    const float* lstm_bih = (const float*)d_in[14];
    const float* lstm_bhh = (const float*)d_in[15];
    const float* ref_w1   = (const float*)d_in[16];
    const float* ref_b1   = (const float*)d_in[17];
    const float* ref_w2   = (const float*)d_in[18];
    const float* ref_b2   = (const float*)d_in[19];

    // opt-in dynamic smem for k_center (d2 array ~61KB + static ~10KB); idempotent
    cudaFuncSetAttribute(k_center, cudaFuncAttributeMaxDynamicSharedMemorySize, 72*1024);

    k_init<<<(BB*NP0*3 + 255)/256, 256>>>(points);

    int N = NP0;
    for(int s=0;s<NSTEPS;s++){
        int P = BB*N;
        k_enc12<<<(P+255)/256, 256>>>(enc_w1, enc_b1, enc_w2, enc_b2, N);
        dim3 g3(BB, N/64);
        k_enc3<<<g3, 256>>>(enc_w3, enc_b3, att_w1, att_b1);
        k_attscore<<<dim3((N+511)/512, BB), 256>>>(att_w1, att_w2, att_b2, N);
        k_center<<<BB, 1024, MAXN*4>>>(N, lstm_wih, lstm_whh, lstm_bih, lstm_bhh,
                                       ref_w1, ref_b1, ref_w2, ref_b2);
        N += NEWP;
    }

    k_cham<<<dim3(93, BB), 256>>>(gt);
    k_final<<<1,1>>>((float*)d_out);
}

// round 8
// speedup vs baseline: 1.1101x; 1.1101x over previous
#include <cuda_runtime.h>
#include <math.h>
#include <float.h>

#define BB 4
#define NP0 4096
#define NEWP 1152
#define MAXN (NP0 + 10*NEWP)     // 15616
#define GD 256
#define HD 128
#define KSEL 64
#define NSTEPS 10
#define REFO (NEWP*3)            // 3456

// ---------------- device scratch (static: no allocation) ----------------
__device__ float    g_canvas[BB][MAXN][3];
__device__ float    g_F2T[128][BB*MAXN];      // encoder layer-2 activations, transposed
__device__ unsigned g_gfenc[BB][GD];
__device__ float    g_h[BB][HD];
__device__ float    g_c[BB][HD];
__device__ float    g_scores[BB][MAXN];
__device__ float    g_center[BB][3];
__device__ float    g_patch[BB][3];
__device__ float    g_hid[BB][HD];
__device__ float    g_attpart[32][BB][128];   // partial bias sums
__device__ double   g_acc[4];

// monotone float<->uint encoding (for atomicMax over signed floats)
__device__ __forceinline__ unsigned fenc(float f){
    unsigned u = __float_as_uint(f);
    return (u & 0x80000000u) ? ~u : (u | 0x80000000u);
}
__device__ __forceinline__ float fdec(unsigned e){
    unsigned u = (e & 0x80000000u) ? (e & 0x7fffffffu) : ~e;
    return __uint_as_float(u);
}

// ---------------- init ----------------
__global__ void k_init(const float* __restrict__ points){
    int i = blockIdx.x*blockDim.x + threadIdx.x;
    if(i < BB*NP0*3){
        int b = i/(NP0*3); int r = i - b*(NP0*3);
        g_canvas[b][r/3][r%3] = points[i];
    }
    if(i < BB*HD){ g_h[i/HD][i%HD] = 0.f; g_c[i/HD][i%HD] = 0.f; }
    if(i < 4) g_acc[i] = 0.0;
}

// ---------------- encoder layers 1-2: tiled smem GEMM (64 pts x 128 ch, K=64) --------
// grid (BB, N/64), block 256, dynamic smem 48KB = w2 (32KB) + f1 tile (16KB).
__global__ void __launch_bounds__(256)
k_enc12(const float* __restrict__ w1, const float* __restrict__ b1,
        const float* __restrict__ w2, const float* __restrict__ b2, int N){
    extern __shared__ float dyn[];
    float* sW2 = dyn;            // [k][j]  64*128
    float* sF1 = dyn + 64*128;   // [k][p]  64*64
    int b = blockIdx.x;
    int pbase = blockIdx.y*64;
    int tid = threadIdx.x;
    if(b==0 && blockIdx.y==0){   // re-init gfeat max accumulators for this step
        for(int i=tid;i<BB*GD;i+=256) ((unsigned*)g_gfenc)[i] = fenc(-FLT_MAX);
    }
    {   // stage w2 (64x128 row-major, contiguous 8192 floats)
        const float4* src = (const float4*)w2;
        float4* dst = (float4*)sW2;
        #pragma unroll
        for(int i=0;i<8;i++) dst[tid + i*256] = src[tid + i*256];
    }
    {   // phase 1: layer-1 f1 for the 64 points (thread = point p, k-group kg)
        int p = tid & 63, kg = tid >> 6;
        int n = pbase + p;
        float x = g_canvas[b][n][0], y = g_canvas[b][n][1], z = g_canvas[b][n][2];
        #pragma unroll
        for(int kk=0;kk<16;kk++){
            int k = kg*16 + kk;
            float f = fmaxf(0.f, b1[k] + x*w1[k] + y*w1[64+k] + z*w1[128+k]);
            sF1[k*64 + p] = f;
        }
    }
    __syncthreads();
    // phase 2: GEMM. thread (lane,pg) -> channels 4*lane..+3, points pg*8..+7
    int lane = tid & 31, pg = tid >> 5;
    int c = lane*4;
    float acc[8][4];
    #pragma unroll
    for(int j=0;j<4;j++){
        float bj = b2[c+j];
        #pragma unroll
        for(int i=0;i<8;i++) acc[i][j] = bj;
    }
    #pragma unroll 4
    for(int k=0;k<64;k++){
        float4 w  = *(const float4*)&sW2[k*128 + c];
        float4 fa = *(const float4*)&sF1[k*64 + pg*8];
        float4 fb = *(const float4*)&sF1[k*64 + pg*8 + 4];
        float f[8] = {fa.x,fa.y,fa.z,fa.w,fb.x,fb.y,fb.z,fb.w};
        #pragma unroll
        for(int i=0;i<8;i++){
            acc[i][0] += f[i]*w.x; acc[i][1] += f[i]*w.y;
            acc[i][2] += f[i]*w.z; acc[i][3] += f[i]*w.w;
        }
    }
    // ReLU + store transposed (coalesced float4 runs of 8 points)
    size_t col0 = (size_t)b*MAXN + pbase + pg*8;
    #pragma unroll
    for(int j=0;j<4;j++){
        float4 v0 = make_float4(fmaxf(acc[0][j],0.f), fmaxf(acc[1][j],0.f),
                                fmaxf(acc[2][j],0.f), fmaxf(acc[3][j],0.f));
        float4 v1 = make_float4(fmaxf(acc[4][j],0.f), fmaxf(acc[5][j],0.f),
                                fmaxf(acc[6][j],0.f), fmaxf(acc[7][j],0.f));
        *(float4*)&g_F2T[c+j][col0]     = v0;
        *(float4*)&g_F2T[c+j][col0 + 4] = v1;
    }
}

// ---------------- encoder layer 3 GEMM + channel max (gfeat) ----------------
// grid (BB, N/64), block 256.  Tile: 64 points x 256 channels.
// K=128 staged through smem in 4 chunks of 32 -> inner loop is pure LDS+FFMA.
__global__ void __launch_bounds__(256,2)
k_enc3(const float* __restrict__ w3, const float* __restrict__ b3){
    __shared__ float sW[32*256];   // [kk][ch]  32KB
    __shared__ float sF[32*64];    // [kk][p]    8KB  (reused as reduce buf)
    int b = blockIdx.x;
    int pbase = blockIdx.y*64;
    int tid = threadIdx.x;
    int lane = tid & 31, pg = tid >> 5;
    int c0 = lane*4, c1 = 128 + lane*4;
    size_t base = (size_t)b*MAXN + pbase;

    float acc[8][8];
    #pragma unroll
    for(int i=0;i<8;i++)
        #pragma unroll
        for(int j=0;j<8;j++) acc[i][j]=0.f;

    for(int kc=0;kc<128;kc+=32){
        __syncthreads();
        {   // stage w3 chunk: rows kc..kc+31 (contiguous 8192 floats)
            const float4* wsrc = (const float4*)(w3 + (size_t)kc*256);
            float4* wdst = (float4*)sW;
            #pragma unroll
            for(int i=0;i<8;i++) wdst[tid + i*256] = wsrc[tid + i*256];
        }
        {   // stage F2T chunk: 32 rows x 64 points
            #pragma unroll
            for(int i=0;i<8;i++){
                int idx = tid + i*256;
                int k = idx>>6, p = idx&63;
                sF[idx] = g_F2T[kc+k][base+p];
            }
        }
        __syncthreads();
        #pragma unroll 4
        for(int k=0;k<32;k++){
            float4 wa = *(const float4*)&sW[k*256 + c0];
            float4 wb = *(const float4*)&sW[k*256 + c1];
            float4 fa = *(const float4*)&sF[k*64 + pg*8];
            float4 fb = *(const float4*)&sF[k*64 + pg*8 + 4];
            float f[8] = {fa.x,fa.y,fa.z,fa.w,fb.x,fb.y,fb.z,fb.w};
            float w[8] = {wa.x,wa.y,wa.z,wa.w,wb.x,wb.y,wb.z,wb.w};
            #pragma unroll
            for(int i=0;i<8;i++)
                #pragma unroll
                for(int j=0;j<8;j++)
                    acc[i][j] += f[i]*w[j];
        }
    }
    // per-thread max over 8 points; +bias (max(a)+b == max(a+b))
    float m[8];
    #pragma unroll
    for(int j=0;j<8;j++){
        float mm = acc[0][j];
        #pragma unroll
        for(int i=1;i<8;i++) mm = fmaxf(mm, acc[i][j]);
        int ch = (j<4) ? (c0+j) : (c1+j-4);
        m[j] = mm + b3[ch];
    }
    __syncthreads();
    #pragma unroll
    for(int j=0;j<8;j++){
        int ch = (j<4) ? (c0+j) : (c1+j-4);
        sF[pg*256 + ch] = m[j];
    }
    __syncthreads();
    {
        int ch = tid;   // 256 channels
        float mm = sF[ch];
        #pragma unroll
        for(int g=1;g<8;g++) mm = fmaxf(mm, sF[g*256 + ch]);
        atomicMax(&g_gfenc[b][ch], fenc(mm));
    }
}

// ---------------- attention bias partials: grid (BB, 32), 128 threads ----------------
__global__ void k_attpre(const float* __restrict__ att_w1, const float* __restrict__ att_b1){
    int b = blockIdx.x, s = blockIdx.y;
    int j = threadIdx.x;
    int r0 = s*12;
    float acc = (s==0) ? att_b1[j] : 0.f;
    #pragma unroll
    for(int kk=0;kk<12;kk++){
        int r = r0 + kk;              // 0..383
        float v = (r < GD) ? fdec(g_gfenc[b][r]) : g_h[b][r-GD];
        acc += v * att_w1[(3+r)*128 + j];
    }
    g_attpart[s][b][j] = acc;
}

// ---------------- attention score: 2 points per thread ----------------
// grid ((N+511)/512, BB), block 256.
__global__ void k_attscore(const float* __restrict__ att_w1, const float* __restrict__ att_w2,
                           const float* __restrict__ att_b2, int N){
    __shared__ float  s_ab[128];
    __shared__ float4 s_pk[128];       // {w1x,w1y,w1z,w2} per hidden unit
    int b = blockIdx.y;
    int tid = threadIdx.x;
    if(tid < 128){
        float a = 0.f;
        #pragma unroll
        for(int s=0;s<32;s++) a += g_attpart[s][b][tid];
        s_ab[tid] = a;
        s_pk[tid] = make_float4(att_w1[tid], att_w1[128+tid], att_w1[256+tid], att_w2[tid]);
    }
    __syncthreads();

    int n0 = blockIdx.x*512 + tid;
    int n1 = n0 + 256;
    bool a0 = n0 < N, a1 = n1 < N;
    float x0=0,y0=0,z0=0,x1=0,y1=0,z1=0;
    if(a0){ x0=g_canvas[b][n0][0]; y0=g_canvas[b][n0][1]; z0=g_canvas[b][n0][2]; }
    if(a1){ x1=g_canvas[b][n1][0]; y1=g_canvas[b][n1][1]; z1=g_canvas[b][n1][2]; }
    float s0 = att_b2[0], s1 = att_b2[0];
    #pragma unroll 4
    for(int jj=0;jj<128;jj++){
        float4 w = s_pk[jj];
        float ab = s_ab[jj];
        float h0 = ab + x0*w.x + y0*w.y + z0*w.z;
        float h1 = ab + x1*w.x + y1*w.y + z1*w.z;
        s0 += fmaxf(h0, 0.f) * w.w;
        s1 += fmaxf(h1, 0.f) * w.w;
    }
    if(a0) g_scores[b][n0] = s0;
    if(a1) g_scores[b][n1] = s1;
}

// ---------------- fused softmax + center + top-K + LSTM + ref1 ----------------
// one block per batch, 1024 threads, dynamic smem = MAXN*4 bytes for d2
__global__ void __launch_bounds__(1024)
k_center(int N,
         const float* __restrict__ wih, const float* __restrict__ whh,
         const float* __restrict__ bih, const float* __restrict__ bhh,
         const float* __restrict__ ref_w1, const float* __restrict__ ref_b1){
    extern __shared__ float sD[];
    __shared__ float rw[32];
    __shared__ int   ri[32];
    __shared__ float s4[32][4];
    __shared__ float s_bc[8];
    __shared__ int   s_itot;
    __shared__ unsigned s_eqn;
    __shared__ int   s_eqi[256];
    __shared__ float s_in[262];
    __shared__ float s_g[512];
    __shared__ float s_hold[HD];
    __shared__ float s_hn[HD];
    int b = blockIdx.x, tid = threadIdx.x;
    int lane = tid & 31, wid = tid >> 5;

    // --- max of scores ---
    float m = -FLT_MAX;
    for(int n=tid;n<N;n+=1024) m = fmaxf(m, g_scores[b][n]);
    #pragma unroll
    for(int o=16;o;o>>=1) m = fmaxf(m, __shfl_xor_sync(0xffffffffu, m, o));
    if(lane==0) rw[wid] = m;
    __syncthreads();
    if(tid==0){
        float mm = rw[0];
        for(int i=1;i<32;i++) mm = fmaxf(mm, rw[i]);
        s_bc[0] = mm;
    }
    __syncthreads();
    float mx = s_bc[0];

    // --- exp sums + weighted coordinate sums ---
    float se=0,sx=0,sy=0,sz=0;
    for(int n=tid;n<N;n+=1024){
        float e = expf(g_scores[b][n]-mx);
        se += e;
        sx += e*g_canvas[b][n][0];
        sy += e*g_canvas[b][n][1];
        sz += e*g_canvas[b][n][2];
    }
    #pragma unroll
    for(int o=16;o;o>>=1){
        se += __shfl_xor_sync(0xffffffffu, se, o);
        sx += __shfl_xor_sync(0xffffffffu, sx, o);
        sy += __shfl_xor_sync(0xffffffffu, sy, o);
        sz += __shfl_xor_sync(0xffffffffu, sz, o);
    }
    if(lane==0){ s4[wid][0]=se; s4[wid][1]=sx; s4[wid][2]=sy; s4[wid][3]=sz; }
    __syncthreads();
    if(tid==0){
        float te=0,tx=0,ty=0,tz=0;
        for(int i=0;i<32;i++){ te+=s4[i][0]; tx+=s4[i][1]; ty+=s4[i][2]; tz+=s4[i][3]; }
        float cx=tx/te, cy=ty/te, cz=tz/te;
        s_bc[1]=cx; s_bc[2]=cy; s_bc[3]=cz;
        g_center[b][0]=cx; g_center[b][1]=cy; g_center[b][2]=cz;
        s_eqn = 0;
    }
    __syncthreads();
    float cx=s_bc[1], cy=s_bc[2], cz=s_bc[3];

    // --- squared distances into smem (monotone with dist -> same top-K) ---
    for(int n=tid;n<N;n+=1024){
        float dx=g_canvas[b][n][0]-cx, dy=g_canvas[b][n][1]-cy, dz=g_canvas[b][n][2]-cz;
        sD[n] = dx*dx+dy*dy+dz*dz;
    }
    __syncthreads();

    // --- binary search on (nonneg) float bits for K-th smallest ---
    unsigned lo=0u, hi=0x7f800000u;
    while(lo < hi){
        unsigned mid = lo + ((hi-lo)>>1);
        int c=0;
        for(int n=tid;n<N;n+=1024) c += (__float_as_uint(sD[n]) <= mid);
        #pragma unroll
        for(int o=16;o;o>>=1) c += __shfl_xor_sync(0xffffffffu, c, o);
        if(lane==0) ri[wid]=c;
        __syncthreads();
        if(tid==0){ int t=0; for(int i=0;i<32;i++) t+=ri[i]; s_itot=t; }
        __syncthreads();
        if(s_itot >= KSEL) hi = mid; else lo = mid+1;
    }
    unsigned u = lo;

    // --- sums of strictly-below + boundary ties (index order matches lax.top_k) ---
    float ax=0,ay=0,az=0; int c=0;
    for(int n=tid;n<N;n+=1024){
        unsigned bits = __float_as_uint(sD[n]);
        if(bits < u){
            c++; ax+=g_canvas[b][n][0]; ay+=g_canvas[b][n][1]; az+=g_canvas[b][n][2];
        }
        if(bits == u){
            unsigned p = atomicAdd(&s_eqn, 1u);
            if(p < 256) s_eqi[p] = n;
        }
    }
    #pragma unroll
    for(int o=16;o;o>>=1){
        c  += __shfl_xor_sync(0xffffffffu, c, o);
        ax += __shfl_xor_sync(0xffffffffu, ax, o);
        ay += __shfl_xor_sync(0xffffffffu, ay, o);
        az += __shfl_xor_sync(0xffffffffu, az, o);
    }
    if(lane==0){ ri[wid]=c; s4[wid][0]=ax; s4[wid][1]=ay; s4[wid][2]=az; }
    __syncthreads();
    if(tid==0){
        int tc=0; float tx=0,ty=0,tz=0;
        for(int i=0;i<32;i++){ tc+=ri[i]; tx+=s4[i][0]; ty+=s4[i][1]; tz+=s4[i][2]; }
        int r = KSEL - tc;                 // boundary elems needed, in index order
        int mcount = min((int)s_eqn, 256);
        for(int it=0; it<r; it++){
            int best=-1, bi=0x7fffffff;
            for(int q=0;q<mcount;q++){ int v=s_eqi[q]; if(v>=0 && v<bi){bi=v;best=q;} }
            if(best<0) break;
            s_eqi[best] = -1;
            tx += g_canvas[b][bi][0]; ty += g_canvas[b][bi][1]; tz += g_canvas[b][bi][2];
        }
        float inv = 1.f/KSEL;
        float px = tx*inv - cx, py = ty*inv - cy, pz = tz*inv - cz;
        g_patch[b][0]=px; g_patch[b][1]=py; g_patch[b][2]=pz;
        s_bc[4]=px; s_bc[5]=py; s_bc[6]=pz;
    }
    __syncthreads();

    // ===== fused LSTM gates + cell + refine layer 1 (this batch only) =====
    for(int i=tid;i<262;i+=1024){
        float v;
        if(i < GD)        v = fdec(g_gfenc[b][i]);
        else if(i < GD+3) v = s_bc[1+i-GD];
        else              v = s_bc[4+i-GD-3];
        s_in[i]=v;
    }
    for(int i=tid;i<HD;i+=1024) s_hold[i]=g_h[b][i];
    __syncthreads();
    if(tid < 512){   // gate j for this batch (same per-(b,j) accumulation order as before)
        int j = tid;
        float a = bih[j] + bhh[j];
        #pragma unroll 2
        for(int k=0;k<262;k++) a += s_in[k]*wih[k*512 + j];
        #pragma unroll 2
        for(int k=0;k<HD;k++)  a += s_hold[k]*whh[k*512 + j];
        s_g[j]=a;
    }
    __syncthreads();
    if(tid < HD){
        int j = tid;
        float gi=s_g[j], gf=s_g[HD+j], gg=s_g[2*HD+j], go=s_g[3*HD+j];
        float sgi=1.f/(1.f+expf(-gi)), sgf=1.f/(1.f+expf(-gf)), sgo=1.f/(1.f+expf(-go));
        float cc = sgf*g_c[b][j] + sgi*tanhf(gg);
        g_c[b][j] = cc;
        float h = sgo*tanhf(cc);
        g_h[b][j] = h;
        s_hn[j] = h;
    }
    __syncthreads();
    if(tid < HD){
        int j = tid;
        float a = ref_b1[j];
        #pragma unroll 2
        for(int k=0;k<HD;k++) a += s_hn[k]*ref_w1[k*128+j];
        g_hid[b][j] = fmaxf(a, 0.f);
    }
}

// ---------------- refine decoder layer 2 -> new canvas points ----------------
__global__ void k_ref2(const float* __restrict__ ref_w2, const float* __restrict__ ref_b2, int N){
    int o = blockIdx.x*256 + threadIdx.x;
    if(o >= BB*REFO) return;
    int b = o/REFO, q = o - b*REFO;
    float a = ref_b2[q];
    const float* h = g_hid[b];
    #pragma unroll 4
    for(int k=0;k<HD;k++) a += h[k]*ref_w2[k*REFO + q];
    int pt = q/3, d = q - 3*pt;
    g_canvas[b][N+pt][d] = a*0.02f + g_center[b][d];
}

// ---------------- chamfer: all 4 directions in one launch ----------------
#define CTI 2048
__global__ void k_cham(const float* __restrict__ gt){
    __shared__ float4 sy[CTI];
    __shared__ float red[256];
    int b = blockIdx.y, tid = threadIdx.x;
    int t = blockIdx.x;
    int dir, tb;
    if(t < 16){ dir=0; tb=t; }
    else if(t < 32){ dir=1; tb=t-16; }
    else if(t < 77){ dir=2; tb=t-32; }
    else { dir=3; tb=t-77; }

    int xsel = (dir==1 || dir==3) ? 1 : 0;           // 0=canvas, 1=gt
    int xoff = (dir==2) ? NP0 : 0;
    int ysel = 1 - xsel;
    int yoff = (dir==3) ? NP0 : 0;
    int Ny   = (dir==3) ? (MAXN-NP0) : NP0;
    int ai   = dir;

    int n = tb*256 + tid;   // all tiles are full
    float x0,x1,x2;
    if(xsel==0){
        x0=g_canvas[b][xoff+n][0]; x1=g_canvas[b][xoff+n][1]; x2=g_canvas[b][xoff+n][2];
    } else {
        const float* p = gt + ((size_t)b*NP0 + n)*3;
        x0=p[0]; x1=p[1]; x2=p[2];
    }
    float xx = x0*x0 + x1*x1 + x2*x2;
    float mn0=FLT_MAX, mn1=FLT_MAX, mn2=FLT_MAX, mn3=FLT_MAX;

    for(int t0=0;t0<Ny;t0+=CTI){
        int cnt = min(CTI, Ny-t0);
        __syncthreads();
        if(ysel==0){
            for(int i=tid;i<cnt;i+=256){
                float y0=g_canvas[b][yoff+t0+i][0], y1=g_canvas[b][yoff+t0+i][1], y2=g_canvas[b][yoff+t0+i][2];
                sy[i] = make_float4(y0,y1,y2, y0*y0+y1*y1+y2*y2);
            }
        } else {
            const float* ys = gt + ((size_t)b*NP0 + t0)*3;
            for(int i=tid;i<cnt;i+=256){
                float y0=ys[3*i], y1=ys[3*i+1], y2=ys[3*i+2];
                sy[i] = make_float4(y0,y1,y2, y0*y0+y1*y1+y2*y2);
            }
        }
        __syncthreads();
        for(int j=0;j<cnt;j+=4){
            float4 A=sy[j], B=sy[j+1], C=sy[j+2], D=sy[j+3];
            float v0 = fmaf(-2.f, fmaf(x0,A.x, fmaf(x1,A.y, x2*A.z)), A.w);
            float v1 = fmaf(-2.f, fmaf(x0,B.x, fmaf(x1,B.y, x2*B.z)), B.w);
            float v2 = fmaf(-2.f, fmaf(x0,C.x, fmaf(x1,C.y, x2*C.z)), C.w);
            float v3 = fmaf(-2.f, fmaf(x0,D.x, fmaf(x1,D.y, x2*D.z)), D.w);
            mn0 = fminf(mn0, v0);
            mn1 = fminf(mn1, v1);
            mn2 = fminf(mn2, v2);
            mn3 = fminf(mn3, v3);
        }
    }
    float mn = fminf(fminf(mn0,mn1), fminf(mn2,mn3));
    red[tid] = xx + mn;
    __syncthreads();
    for(int s=128;s>0;s>>=1){ if(tid<s) red[tid]+=red[tid+s]; __syncthreads(); }
    if(tid==0) atomicAdd(&g_acc[ai], (double)red[0]);
}

__global__ void k_final(float* __restrict__ out){
    double cd_in  = g_acc[0]/(4.0*NP0)          + g_acc[1]/(4.0*NP0);
    double cd_new = g_acc[2]/(4.0*(10.0*NEWP))  + g_acc[3]/(4.0*NP0);
    out[0] = (float)(0.1*cd_in + 1.0*cd_new);
}

// ---------------- host launch ----------------
extern "C" void kernel_launch(void* const* d_in, const int* in_sizes, int n_in,
                              void* d_out, int out_size){
    const float* points   = (const float*)d_in[0];
    const float* gt       = (const float*)d_in[1];
    const float* enc_w1   = (const float*)d_in[2];
    const float* enc_b1   = (const float*)d_in[3];
    const float* enc_w2   = (const float*)d_in[4];
    const float* enc_b2   = (const float*)d_in[5];
    const float* enc_w3   = (const float*)d_in[6];
    const float* enc_b3   = (const float*)d_in[7];
    const float* att_w1   = (const float*)d_in[8];
    const float* att_b1   = (const float*)d_in[9];
    const float* att_w2   = (const float*)d_in[10];
    const float* att_b2   = (const float*)d_in[11];
    const float* lstm_wih = (const float*)d_in[12];
    const float* lstm_whh = (const float*)d_in[13];
    const float* lstm_bih = (const float*)d_in[14];
    const float* lstm_bhh = (const float*)d_in[15];
    const float* ref_w1   = (const float*)d_in[16];
    const float* ref_b1   = (const float*)d_in[17];
    const float* ref_w2   = (const float*)d_in[18];
    const float* ref_b2   = (const float*)d_in[19];

    // opt-in dynamic smem (idempotent, capture-safe)
    cudaFuncSetAttribute(k_center, cudaFuncAttributeMaxDynamicSharedMemorySize, 64*1024);
    cudaFuncSetAttribute(k_enc12,  cudaFuncAttributeMaxDynamicSharedMemorySize, 48*1024);

    k_init<<<(BB*NP0*3 + 255)/256, 256>>>(points);

    int N = NP0;
    for(int s=0;s<NSTEPS;s++){
        dim3 gt12(BB, N/64);
        k_enc12<<<gt12, 256, 48*1024>>>(enc_w1, enc_b1, enc_w2, enc_b2, N);
        dim3 g3(BB, N/64);
        k_enc3<<<g3, 256>>>(enc_w3, enc_b3);
        k_attpre<<<dim3(BB,32), 128>>>(att_w1, att_b1);
        k_attscore<<<dim3((N+511)/512, BB), 256>>>(att_w1, att_w2, att_b2, N);
        k_center<<<BB, 1024, MAXN*4>>>(N, lstm_wih, lstm_whh, lstm_bih, lstm_bhh, ref_w1, ref_b1);
        k_ref2<<<(BB*REFO+255)/256, 256>>>(ref_w2, ref_b2, N);
        N += NEWP;
    }

    k_cham<<<dim3(93, BB), 256>>>(gt);
    k_final<<<1,1>>>((float*)d_out);
}

// round 9
// speedup vs baseline: 1.5551x; 1.4008x over previous
#include <cuda_runtime.h>
#include <math.h>
#include <float.h>

#define BB 4
#define NP0 4096
#define NEWP 1152
#define MAXN (NP0 + 10*NEWP)     // 15616
#define GD 256
#define HD 128
#define KSEL 64
#define NSTEPS 10
#define REFO (NEWP*3)            // 3456

// ---------------- device scratch (static: no allocation) ----------------
__device__ float    g_canvas[BB][MAXN][3];
__device__ float    g_F2T[128][BB*MAXN];      // encoder layer-2 activations, transposed
__device__ unsigned g_gfenc[BB][GD];          // RUNNING max across steps (canvas only grows)
__device__ float    g_h[BB][HD];
__device__ float    g_c[BB][HD];
__device__ float    g_scores[BB][MAXN];
__device__ float    g_center[BB][3];
__device__ float    g_patch[BB][3];
__device__ float    g_hid[BB][HD];
__device__ float    g_attpart[32][BB][128];   // partial bias sums
__device__ double   g_acc[4];

// monotone float<->uint encoding (for atomicMax over signed floats)
__device__ __forceinline__ unsigned fenc(float f){
    unsigned u = __float_as_uint(f);
    return (u & 0x80000000u) ? ~u : (u | 0x80000000u);
}
__device__ __forceinline__ float fdec(unsigned e){
    unsigned u = (e & 0x80000000u) ? (e & 0x7fffffffu) : ~e;
    return __uint_as_float(u);
}

// ---------------- init ----------------
__global__ void k_init(const float* __restrict__ points){
    int i = blockIdx.x*blockDim.x + threadIdx.x;
    if(i < BB*NP0*3){
        int b = i/(NP0*3); int r = i - b*(NP0*3);
        g_canvas[b][r/3][r%3] = points[i];
    }
    if(i < BB*HD){ g_h[i/HD][i%HD] = 0.f; g_c[i/HD][i%HD] = 0.f; }
    if(i < BB*GD) ((unsigned*)g_gfenc)[i] = fenc(-FLT_MAX);   // once: running max
    if(i < 4) g_acc[i] = 0.0;
}

// ---------------- encoder layers 1-2: tiled smem GEMM (64 pts x 128 ch, K=64) --------
// Encodes ONLY points [p0 + 64*blockIdx.y, +64) — new points of this step.
// grid (BB, cnt/64), block 256, dynamic smem 48KB = w2 (32KB) + f1 tile (16KB).
__global__ void __launch_bounds__(256)
k_enc12(const float* __restrict__ w1, const float* __restrict__ b1,
        const float* __restrict__ w2, const float* __restrict__ b2, int p0){
    extern __shared__ float dyn[];
    float* sW2 = dyn;            // [k][j]  64*128
    float* sF1 = dyn + 64*128;   // [k][p]  64*64
    int b = blockIdx.x;
    int pbase = p0 + blockIdx.y*64;
    int tid = threadIdx.x;
    {   // stage w2 (64x128 row-major, contiguous 8192 floats)
        const float4* src = (const float4*)w2;
        float4* dst = (float4*)sW2;
        #pragma unroll
        for(int i=0;i<8;i++) dst[tid + i*256] = src[tid + i*256];
    }
    {   // phase 1: layer-1 f1 for the 64 points (thread = point p, k-group kg)
        int p = tid & 63, kg = tid >> 6;
        int n = pbase + p;
        float x = g_canvas[b][n][0], y = g_canvas[b][n][1], z = g_canvas[b][n][2];
        #pragma unroll
        for(int kk=0;kk<16;kk++){
            int k = kg*16 + kk;
            float f = fmaxf(0.f, b1[k] + x*w1[k] + y*w1[64+k] + z*w1[128+k]);
            sF1[k*64 + p] = f;
        }
    }
    __syncthreads();
    // phase 2: GEMM. thread (lane,pg) -> channels 4*lane..+3, points pg*8..+7
    int lane = tid & 31, pg = tid >> 5;
    int c = lane*4;
    float acc[8][4];
    #pragma unroll
    for(int j=0;j<4;j++){
        float bj = b2[c+j];
        #pragma unroll
        for(int i=0;i<8;i++) acc[i][j] = bj;
    }
    #pragma unroll 4
    for(int k=0;k<64;k++){
        float4 w  = *(const float4*)&sW2[k*128 + c];
        float4 fa = *(const float4*)&sF1[k*64 + pg*8];
        float4 fb = *(const float4*)&sF1[k*64 + pg*8 + 4];
        float f[8] = {fa.x,fa.y,fa.z,fa.w,fb.x,fb.y,fb.z,fb.w};
        #pragma unroll
        for(int i=0;i<8;i++){
            acc[i][0] += f[i]*w.x; acc[i][1] += f[i]*w.y;
            acc[i][2] += f[i]*w.z; acc[i][3] += f[i]*w.w;
        }
    }
    // ReLU + store transposed (coalesced float4 runs of 8 points)
    size_t col0 = (size_t)b*MAXN + pbase + pg*8;
    #pragma unroll
    for(int j=0;j<4;j++){
        float4 v0 = make_float4(fmaxf(acc[0][j],0.f), fmaxf(acc[1][j],0.f),
                                fmaxf(acc[2][j],0.f), fmaxf(acc[3][j],0.f));
        float4 v1 = make_float4(fmaxf(acc[4][j],0.f), fmaxf(acc[5][j],0.f),
                                fmaxf(acc[6][j],0.f), fmaxf(acc[7][j],0.f));
        *(float4*)&g_F2T[c+j][col0]     = v0;
        *(float4*)&g_F2T[c+j][col0 + 4] = v1;
    }
}

// ---------------- encoder layer 3 GEMM + channel max into RUNNING gfeat --------------
// grid (BB, cnt/64), block 256.  Tile: 64 points x 256 channels, K=128 smem-staged.
__global__ void __launch_bounds__(256,2)
k_enc3(const float* __restrict__ w3, const float* __restrict__ b3, int p0){
    __shared__ float sW[32*256];   // [kk][ch]  32KB
    __shared__ float sF[32*64];    // [kk][p]    8KB  (reused as reduce buf)
    int b = blockIdx.x;
    int pbase = p0 + blockIdx.y*64;
    int tid = threadIdx.x;
    int lane = tid & 31, pg = tid >> 5;
    int c0 = lane*4, c1 = 128 + lane*4;
    size_t base = (size_t)b*MAXN + pbase;

    float acc[8][8];
    #pragma unroll
    for(int i=0;i<8;i++)
        #pragma unroll
        for(int j=0;j<8;j++) acc[i][j]=0.f;

    for(int kc=0;kc<128;kc+=32){
        __syncthreads();
        {   // stage w3 chunk: rows kc..kc+31 (contiguous 8192 floats)
            const float4* wsrc = (const float4*)(w3 + (size_t)kc*256);
            float4* wdst = (float4*)sW;
            #pragma unroll
            for(int i=0;i<8;i++) wdst[tid + i*256] = wsrc[tid + i*256];
        }
        {   // stage F2T chunk: 32 rows x 64 points
            #pragma unroll
            for(int i=0;i<8;i++){
                int idx = tid + i*256;
                int k = idx>>6, p = idx&63;
                sF[idx] = g_F2T[kc+k][base+p];
            }
        }
        __syncthreads();
        #pragma unroll 4
        for(int k=0;k<32;k++){
            float4 wa = *(const float4*)&sW[k*256 + c0];
            float4 wb = *(const float4*)&sW[k*256 + c1];
            float4 fa = *(const float4*)&sF[k*64 + pg*8];
            float4 fb = *(const float4*)&sF[k*64 + pg*8 + 4];
            float f[8] = {fa.x,fa.y,fa.z,fa.w,fb.x,fb.y,fb.z,fb.w};
            float w[8] = {wa.x,wa.y,wa.z,wa.w,wb.x,wb.y,wb.z,wb.w};
            #pragma unroll
            for(int i=0;i<8;i++)
                #pragma unroll
                for(int j=0;j<8;j++)
                    acc[i][j] += f[i]*w[j];
        }
    }
    // per-thread max over 8 points; +bias (max(a)+b == max(a+b))
    float m[8];
    #pragma unroll
    for(int j=0;j<8;j++){
        float mm = acc[0][j];
        #pragma unroll
        for(int i=1;i<8;i++) mm = fmaxf(mm, acc[i][j]);
        int ch = (j<4) ? (c0+j) : (c1+j-4);
        m[j] = mm + b3[ch];
    }
    __syncthreads();
    #pragma unroll
    for(int j=0;j<8;j++){
        int ch = (j<4) ? (c0+j) : (c1+j-4);
        sF[pg*256 + ch] = m[j];
    }
    __syncthreads();
    {
        int ch = tid;   // 256 channels
        float mm = sF[ch];
        #pragma unroll
        for(int g=1;g<8;g++) mm = fmaxf(mm, sF[g*256 + ch]);
        atomicMax(&g_gfenc[b][ch], fenc(mm));   // running max across steps
    }
}

// ---------------- attention bias partials: grid (BB, 32), 128 threads ----------------
__global__ void k_attpre(const float* __restrict__ att_w1, const float* __restrict__ att_b1){
    int b = blockIdx.x, s = blockIdx.y;
    int j = threadIdx.x;
    int r0 = s*12;
    float acc = (s==0) ? att_b1[j] : 0.f;
    #pragma unroll
    for(int kk=0;kk<12;kk++){
        int r = r0 + kk;              // 0..383
        float v = (r < GD) ? fdec(g_gfenc[b][r]) : g_h[b][r-GD];
        acc += v * att_w1[(3+r)*128 + j];
    }
    g_attpart[s][b][j] = acc;
}

// ---------------- attention score: 2 points per thread ----------------
// grid ((N+511)/512, BB), block 256.
__global__ void k_attscore(const float* __restrict__ att_w1, const float* __restrict__ att_w2,
                           const float* __restrict__ att_b2, int N){
    __shared__ float  s_ab[128];
    __shared__ float4 s_pk[128];       // {w1x,w1y,w1z,w2} per hidden unit
    int b = blockIdx.y;
    int tid = threadIdx.x;
    if(tid < 128){
        float a = 0.f;
        #pragma unroll
        for(int s=0;s<32;s++) a += g_attpart[s][b][tid];
        s_ab[tid] = a;
        s_pk[tid] = make_float4(att_w1[tid], att_w1[128+tid], att_w1[256+tid], att_w2[tid]);
    }
    __syncthreads();

    int n0 = blockIdx.x*512 + tid;
    int n1 = n0 + 256;
    bool a0 = n0 < N, a1 = n1 < N;
    float x0=0,y0=0,z0=0,x1=0,y1=0,z1=0;
    if(a0){ x0=g_canvas[b][n0][0]; y0=g_canvas[b][n0][1]; z0=g_canvas[b][n0][2]; }
    if(a1){ x1=g_canvas[b][n1][0]; y1=g_canvas[b][n1][1]; z1=g_canvas[b][n1][2]; }
    float s0 = att_b2[0], s1 = att_b2[0];
    #pragma unroll 4
    for(int jj=0;jj<128;jj++){
        float4 w = s_pk[jj];
        float ab = s_ab[jj];
        float h0 = ab + x0*w.x + y0*w.y + z0*w.z;
        float h1 = ab + x1*w.x + y1*w.y + z1*w.z;
        s0 += fmaxf(h0, 0.f) * w.w;
        s1 += fmaxf(h1, 0.f) * w.w;
    }
    if(a0) g_scores[b][n0] = s0;
    if(a1) g_scores[b][n1] = s1;
}

// ---------------- fused softmax + center + top-K + LSTM + ref1 ----------------
// one block per batch, 1024 threads, dynamic smem = MAXN*4 bytes for d2
__global__ void __launch_bounds__(1024)
k_center(int N,
         const float* __restrict__ wih, const float* __restrict__ whh,
         const float* __restrict__ bih, const float* __restrict__ bhh,
         const float* __restrict__ ref_w1, const float* __restrict__ ref_b1){
    extern __shared__ float sD[];
    __shared__ float rw[32];
    __shared__ int   ri[32];
    __shared__ float s4[32][4];
    __shared__ float s_bc[8];
    __shared__ int   s_itot;
    __shared__ unsigned s_eqn;
    __shared__ int   s_eqi[256];
    __shared__ float s_in[262];
    __shared__ float s_g[512];
    __shared__ float s_hold[HD];
    __shared__ float s_hn[HD];
    int b = blockIdx.x, tid = threadIdx.x;
    int lane = tid & 31, wid = tid >> 5;

    // --- max of scores ---
    float m = -FLT_MAX;
    for(int n=tid;n<N;n+=1024) m = fmaxf(m, g_scores[b][n]);
    #pragma unroll
    for(int o=16;o;o>>=1) m = fmaxf(m, __shfl_xor_sync(0xffffffffu, m, o));
    if(lane==0) rw[wid] = m;
    __syncthreads();
    if(tid==0){
        float mm = rw[0];
        for(int i=1;i<32;i++) mm = fmaxf(mm, rw[i]);
        s_bc[0] = mm;
    }
    __syncthreads();
    float mx = s_bc[0];

    // --- exp sums + weighted coordinate sums ---
    float se=0,sx=0,sy=0,sz=0;
    for(int n=tid;n<N;n+=1024){
        float e = expf(g_scores[b][n]-mx);
        se += e;
        sx += e*g_canvas[b][n][0];
        sy += e*g_canvas[b][n][1];
        sz += e*g_canvas[b][n][2];
    }
    #pragma unroll
    for(int o=16;o;o>>=1){
        se += __shfl_xor_sync(0xffffffffu, se, o);
        sx += __shfl_xor_sync(0xffffffffu, sx, o);
        sy += __shfl_xor_sync(0xffffffffu, sy, o);
        sz += __shfl_xor_sync(0xffffffffu, sz, o);
    }
    if(lane==0){ s4[wid][0]=se; s4[wid][1]=sx; s4[wid][2]=sy; s4[wid][3]=sz; }
    __syncthreads();
    if(tid==0){
        float te=0,tx=0,ty=0,tz=0;
        for(int i=0;i<32;i++){ te+=s4[i][0]; tx+=s4[i][1]; ty+=s4[i][2]; tz+=s4[i][3]; }
        float cx=tx/te, cy=ty/te, cz=tz/te;
        s_bc[1]=cx; s_bc[2]=cy; s_bc[3]=cz;
        g_center[b][0]=cx; g_center[b][1]=cy; g_center[b][2]=cz;
        s_eqn = 0;
    }
    __syncthreads();
    float cx=s_bc[1], cy=s_bc[2], cz=s_bc[3];

    // --- squared distances into smem (monotone with dist -> same top-K) ---
    for(int n=tid;n<N;n+=1024){
        float dx=g_canvas[b][n][0]-cx, dy=g_canvas[b][n][1]-cy, dz=g_canvas[b][n][2]-cz;
        sD[n] = dx*dx+dy*dy+dz*dz;
    }
    __syncthreads();

    // --- binary search on (nonneg) float bits for K-th smallest ---
    unsigned lo=0u, hi=0x7f800000u;
    while(lo < hi){
        unsigned mid = lo + ((hi-lo)>>1);
        int c=0;
        for(int n=tid;n<N;n+=1024) c += (__float_as_uint(sD[n]) <= mid);
        #pragma unroll
        for(int o=16;o;o>>=1) c += __shfl_xor_sync(0xffffffffu, c, o);
        if(lane==0) ri[wid]=c;
        __syncthreads();
        if(tid==0){ int t=0; for(int i=0;i<32;i++) t+=ri[i]; s_itot=t; }
        __syncthreads();
        if(s_itot >= KSEL) hi = mid; else lo = mid+1;
    }
    unsigned u = lo;

    // --- sums of strictly-below + boundary ties (index order matches lax.top_k) ---
    float ax=0,ay=0,az=0; int c=0;
    for(int n=tid;n<N;n+=1024){
        unsigned bits = __float_as_uint(sD[n]);
        if(bits < u){
            c++; ax+=g_canvas[b][n][0]; ay+=g_canvas[b][n][1]; az+=g_canvas[b][n][2];
        }
        if(bits == u){
            unsigned p = atomicAdd(&s_eqn, 1u);
            if(p < 256) s_eqi[p] = n;
        }
    }
    #pragma unroll
    for(int o=16;o;o>>=1){
        c  += __shfl_xor_sync(0xffffffffu, c, o);
        ax += __shfl_xor_sync(0xffffffffu, ax, o);
        ay += __shfl_xor_sync(0xffffffffu, ay, o);
        az += __shfl_xor_sync(0xffffffffu, az, o);
    }
    if(lane==0){ ri[wid]=c; s4[wid][0]=ax; s4[wid][1]=ay; s4[wid][2]=az; }
    __syncthreads();
    if(tid==0){
        int tc=0; float tx=0,ty=0,tz=0;
        for(int i=0;i<32;i++){ tc+=ri[i]; tx+=s4[i][0]; ty+=s4[i][1]; tz+=s4[i][2]; }
        int r = KSEL - tc;                 // boundary elems needed, in index order
        int mcount = min((int)s_eqn, 256);
        for(int it=0; it<r; it++){
            int best=-1, bi=0x7fffffff;
            for(int q=0;q<mcount;q++){ int v=s_eqi[q]; if(v>=0 && v<bi){bi=v;best=q;} }
            if(best<0) break;
            s_eqi[best] = -1;
            tx += g_canvas[b][bi][0]; ty += g_canvas[b][bi][1]; tz += g_canvas[b][bi][2];
        }
        float inv = 1.f/KSEL;
        float px = tx*inv - cx, py = ty*inv - cy, pz = tz*inv - cz;
        g_patch[b][0]=px; g_patch[b][1]=py; g_patch[b][2]=pz;
        s_bc[4]=px; s_bc[5]=py; s_bc[6]=pz;
    }
    __syncthreads();

    // ===== fused LSTM gates + cell + refine layer 1 (this batch only) =====
    for(int i=tid;i<262;i+=1024){
        float v;
        if(i < GD)        v = fdec(g_gfenc[b][i]);
        else if(i < GD+3) v = s_bc[1+i-GD];
        else              v = s_bc[4+i-GD-3];
        s_in[i]=v;
    }
    for(int i=tid;i<HD;i+=1024) s_hold[i]=g_h[b][i];
    __syncthreads();
    if(tid < 512){   // gate j for this batch (same per-(b,j) accumulation order as before)
        int j = tid;
        float a = bih[j] + bhh[j];
        #pragma unroll 2
        for(int k=0;k<262;k++) a += s_in[k]*wih[k*512 + j];
        #pragma unroll 2
        for(int k=0;k<HD;k++)  a += s_hold[k]*whh[k*512 + j];
        s_g[j]=a;
    }
    __syncthreads();
    if(tid < HD){
        int j = tid;
        float gi=s_g[j], gf=s_g[HD+j], gg=s_g[2*HD+j], go=s_g[3*HD+j];
        float sgi=1.f/(1.f+expf(-gi)), sgf=1.f/(1.f+expf(-gf)), sgo=1.f/(1.f+expf(-go));
        float cc = sgf*g_c[b][j] + sgi*tanhf(gg);
        g_c[b][j] = cc;
        float h = sgo*tanhf(cc);
        g_h[b][j] = h;
        s_hn[j] = h;
    }
    __syncthreads();
    if(tid < HD){
        int j = tid;
        float a = ref_b1[j];
        #pragma unroll 2
        for(int k=0;k<HD;k++) a += s_hn[k]*ref_w1[k*128+j];
        g_hid[b][j] = fmaxf(a, 0.f);
    }
}

// ---------------- refine decoder layer 2 -> new canvas points ----------------
__global__ void k_ref2(const float* __restrict__ ref_w2, const float* __restrict__ ref_b2, int N){
    int o = blockIdx.x*256 + threadIdx.x;
    if(o >= BB*REFO) return;
    int b = o/REFO, q = o - b*REFO;
    float a = ref_b2[q];
    const float* h = g_hid[b];
    #pragma unroll 4
    for(int k=0;k<HD;k++) a += h[k]*ref_w2[k*REFO + q];
    int pt = q/3, d = q - 3*pt;
    g_canvas[b][N+pt][d] = a*0.02f + g_center[b][d];
}

// ---------------- chamfer: all 4 directions in one launch ----------------
#define CTI 2048
__global__ void k_cham(const float* __restrict__ gt){
    __shared__ float4 sy[CTI];
    __shared__ float red[256];
    int b = blockIdx.y, tid = threadIdx.x;
    int t = blockIdx.x;
    int dir, tb;
    if(t < 16){ dir=0; tb=t; }
    else if(t < 32){ dir=1; tb=t-16; }
    else if(t < 77){ dir=2; tb=t-32; }
    else { dir=3; tb=t-77; }

    int xsel = (dir==1 || dir==3) ? 1 : 0;           // 0=canvas, 1=gt
    int xoff = (dir==2) ? NP0 : 0;
    int ysel = 1 - xsel;
    int yoff = (dir==3) ? NP0 : 0;
    int Ny   = (dir==3) ? (MAXN-NP0) : NP0;
    int ai   = dir;

    int n = tb*256 + tid;   // all tiles are full
    float x0,x1,x2;
    if(xsel==0){
        x0=g_canvas[b][xoff+n][0]; x1=g_canvas[b][xoff+n][1]; x2=g_canvas[b][xoff+n][2];
    } else {
        const float* p = gt + ((size_t)b*NP0 + n)*3;
        x0=p[0]; x1=p[1]; x2=p[2];
    }
    float xx = x0*x0 + x1*x1 + x2*x2;
    float mn0=FLT_MAX, mn1=FLT_MAX, mn2=FLT_MAX, mn3=FLT_MAX;

    for(int t0=0;t0<Ny;t0+=CTI){
        int cnt = min(CTI, Ny-t0);
        __syncthreads();
        if(ysel==0){
            for(int i=tid;i<cnt;i+=256){
                float y0=g_canvas[b][yoff+t0+i][0], y1=g_canvas[b][yoff+t0+i][1], y2=g_canvas[b][yoff+t0+i][2];
                sy[i] = make_float4(y0,y1,y2, y0*y0+y1*y1+y2*y2);
            }
        } else {
            const float* ys = gt + ((size_t)b*NP0 + t0)*3;
            for(int i=tid;i<cnt;i+=256){
                float y0=ys[3*i], y1=ys[3*i+1], y2=ys[3*i+2];
                sy[i] = make_float4(y0,y1,y2, y0*y0+y1*y1+y2*y2);
            }
        }
        __syncthreads();
        for(int j=0;j<cnt;j+=4){
            float4 A=sy[j], B=sy[j+1], C=sy[j+2], D=sy[j+3];
            float v0 = fmaf(-2.f, fmaf(x0,A.x, fmaf(x1,A.y, x2*A.z)), A.w);
            float v1 = fmaf(-2.f, fmaf(x0,B.x, fmaf(x1,B.y, x2*B.z)), B.w);
            float v2 = fmaf(-2.f, fmaf(x0,C.x, fmaf(x1,C.y, x2*C.z)), C.w);
            float v3 = fmaf(-2.f, fmaf(x0,D.x, fmaf(x1,D.y, x2*D.z)), D.w);
            mn0 = fminf(mn0, v0);
            mn1 = fminf(mn1, v1);
            mn2 = fminf(mn2, v2);
            mn3 = fminf(mn3, v3);
        }
    }
    float mn = fminf(fminf(mn0,mn1), fminf(mn2,mn3));
    red[tid] = xx + mn;
    __syncthreads();
    for(int s=128;s>0;s>>=1){ if(tid<s) red[tid]+=red[tid+s]; __syncthreads(); }
    if(tid==0) atomicAdd(&g_acc[ai], (double)red[0]);
}

__global__ void k_final(float* __restrict__ out){
    double cd_in  = g_acc[0]/(4.0*NP0)          + g_acc[1]/(4.0*NP0);
    double cd_new = g_acc[2]/(4.0*(10.0*NEWP))  + g_acc[3]/(4.0*NP0);
    out[0] = (float)(0.1*cd_in + 1.0*cd_new);
}

// ---------------- host launch ----------------
extern "C" void kernel_launch(void* const* d_in, const int* in_sizes, int n_in,
                              void* d_out, int out_size){
    const float* points   = (const float*)d_in[0];
    const float* gt       = (const float*)d_in[1];
    const float* enc_w1   = (const float*)d_in[2];
    const float* enc_b1   = (const float*)d_in[3];
    const float* enc_w2   = (const float*)d_in[4];
    const float* enc_b2   = (const float*)d_in[5];
    const float* enc_w3   = (const float*)d_in[6];
    const float* enc_b3   = (const float*)d_in[7];
    const float* att_w1   = (const float*)d_in[8];
    const float* att_b1   = (const float*)d_in[9];
    const float* att_w2   = (const float*)d_in[10];
    const float* att_b2   = (const float*)d_in[11];
    const float* lstm_wih = (const float*)d_in[12];
    const float* lstm_whh = (const float*)d_in[13];
    const float* lstm_bih = (const float*)d_in[14];
    const float* lstm_bhh = (const float*)d_in[15];
    const float* ref_w1   = (const float*)d_in[16];
    const float* ref_b1   = (const float*)d_in[17];
    const float* ref_w2   = (const float*)d_in[18];
    const float* ref_b2   = (const float*)d_in[19];

    // opt-in dynamic smem (idempotent, capture-safe)
    cudaFuncSetAttribute(k_center, cudaFuncAttributeMaxDynamicSharedMemorySize, 64*1024);
    cudaFuncSetAttribute(k_enc12,  cudaFuncAttributeMaxDynamicSharedMemorySize, 48*1024);

    k_init<<<(BB*NP0*3 + 255)/256, 256>>>(points);

    int N = NP0;
    for(int s=0;s<NSTEPS;s++){
        // Incremental encoding: canvas only grows and encoder weights are fixed,
        // so only the points appended last step need encoding; gfeat is a running max.
        int e0   = (s==0) ? 0   : (N - NEWP);
        int ecnt = (s==0) ? NP0 : NEWP;
        dim3 ge(BB, ecnt/64);
        k_enc12<<<ge, 256, 48*1024>>>(enc_w1, enc_b1, enc_w2, enc_b2, e0);
        k_enc3<<<ge, 256>>>(enc_w3, enc_b3, e0);
        k_attpre<<<dim3(BB,32), 128>>>(att_w1, att_b1);
        k_attscore<<<dim3((N+511)/512, BB), 256>>>(att_w1, att_w2, att_b2, N);
        k_center<<<BB, 1024, MAXN*4>>>(N, lstm_wih, lstm_whh, lstm_bih, lstm_bhh, ref_w1, ref_b1);
        k_ref2<<<(BB*REFO+255)/256, 256>>>(ref_w2, ref_b2, N);
        N += NEWP;
    }

    k_cham<<<dim3(93, BB), 256>>>(gt);
    k_final<<<1,1>>>((float*)d_out);
}

// round 10
// speedup vs baseline: 1.8470x; 1.1877x over previous
#include <cuda_runtime.h>
#include <math.h>
#include <float.h>

#define BB 4
#define NP0 4096
#define NEWP 1152
#define MAXN (NP0 + 10*NEWP)     // 15616
#define GD 256
#define HD 128
#define KSEL 64
#define NSTEPS 10
#define REFO (NEWP*3)            // 3456

// ---------------- device scratch (static: no allocation) ----------------
__device__ float    g_canvas[BB][MAXN][3];
__device__ unsigned g_gfenc[BB][GD];          // RUNNING max across steps (canvas only grows)
__device__ float    g_h[BB][HD];
__device__ float    g_c[BB][HD];
__device__ float    g_scores[BB][MAXN];
__device__ float    g_center[BB][3];
__device__ float    g_patch[BB][3];
__device__ float    g_hid[BB][HD];
__device__ float    g_attpart[32][BB][128];   // partial bias sums
__device__ double   g_acc[4];

// monotone float<->uint encoding (for atomicMax over signed floats)
__device__ __forceinline__ unsigned fenc(float f){
    unsigned u = __float_as_uint(f);
    return (u & 0x80000000u) ? ~u : (u | 0x80000000u);
}
__device__ __forceinline__ float fdec(unsigned e){
    unsigned u = (e & 0x80000000u) ? (e & 0x7fffffffu) : ~e;
    return __uint_as_float(u);
}

// ---------------- init ----------------
__global__ void k_init(const float* __restrict__ points){
    int i = blockIdx.x*blockDim.x + threadIdx.x;
    if(i < BB*NP0*3){
        int b = i/(NP0*3); int r = i - b*(NP0*3);
        g_canvas[b][r/3][r%3] = points[i];
    }
    if(i < BB*HD){ g_h[i/HD][i%HD] = 0.f; g_c[i/HD][i%HD] = 0.f; }
    if(i < BB*GD) ((unsigned*)g_gfenc)[i] = fenc(-FLT_MAX);   // once: running max
    if(i < 4) g_acc[i] = 0.0;
}

// ---------------- FUSED encoder (layers 1-3 + channel max into running gfeat) -------
// grid (BB, cnt/64), block 256, dynamic smem 80KB:
//   sW  [8192]  : w2, then w3 chunks (32KB)
//   sF2 [8192]  : layer-2 activations [k][p], XOR-swizzled (32KB)
//   sF1 [4096]  : layer-1 activations [k][p] (16KB); reused as reduce buffer
// f2 swizzle: element (r, p) stored at r*64 + (p ^ (((r>>2)&7)*8))
__global__ void __launch_bounds__(256,2)
k_enc(const float* __restrict__ w1, const float* __restrict__ b1,
      const float* __restrict__ w2, const float* __restrict__ b2,
      const float* __restrict__ w3, const float* __restrict__ b3, int p0){
    extern __shared__ float dyn[];
    float* sW  = dyn;
    float* sF2 = dyn + 8192;
    float* sF1 = dyn + 16384;
    int b = blockIdx.x;
    int pbase = p0 + blockIdx.y*64;
    int tid = threadIdx.x, lane = tid & 31, pg = tid >> 5;

    {   // stage w2 (64x128 row-major, contiguous 8192 floats)
        const float4* src = (const float4*)w2;
        float4* dst = (float4*)sW;
        #pragma unroll
        for(int i=0;i<8;i++) dst[tid + i*256] = src[tid + i*256];
    }
    {   // layer 1: f1 for the 64 points (thread = point p, k-group kg)
        int p = tid & 63, kg = tid >> 6;
        int n = pbase + p;
        float x = g_canvas[b][n][0], y = g_canvas[b][n][1], z = g_canvas[b][n][2];
        #pragma unroll
        for(int kk=0;kk<16;kk++){
            int k = kg*16 + kk;
            float f = fmaxf(0.f, b1[k] + x*w1[k] + y*w1[64+k] + z*w1[128+k]);
            sF1[k*64 + p] = f;
        }
    }
    __syncthreads();
    {   // layer 2 GEMM: thread (lane,pg) -> channels 4*lane..+3, points pg*8..+7
        int c = lane*4;
        float acc[8][4];
        #pragma unroll
        for(int j=0;j<4;j++){
            float bj = b2[c+j];
            #pragma unroll
            for(int i=0;i<8;i++) acc[i][j] = bj;
        }
        #pragma unroll 4
        for(int k=0;k<64;k++){
            float4 w  = *(const float4*)&sW[k*128 + c];
            float4 fa = *(const float4*)&sF1[k*64 + pg*8];
            float4 fb = *(const float4*)&sF1[k*64 + pg*8 + 4];
            float f[8] = {fa.x,fa.y,fa.z,fa.w,fb.x,fb.y,fb.z,fb.w};
            #pragma unroll
            for(int i=0;i<8;i++){
                acc[i][0] += f[i]*w.x; acc[i][1] += f[i]*w.y;
                acc[i][2] += f[i]*w.z; acc[i][3] += f[i]*w.w;
            }
        }
        // ReLU + store to swizzled sF2 (rows c..c+3; (r>>2)&7 == lane&7)
        int scol = (pg*8) ^ ((lane & 7) * 8);
        #pragma unroll
        for(int j=0;j<4;j++){
            float4 v0 = make_float4(fmaxf(acc[0][j],0.f), fmaxf(acc[1][j],0.f),
                                    fmaxf(acc[2][j],0.f), fmaxf(acc[3][j],0.f));
            float4 v1 = make_float4(fmaxf(acc[4][j],0.f), fmaxf(acc[5][j],0.f),
                                    fmaxf(acc[6][j],0.f), fmaxf(acc[7][j],0.f));
            *(float4*)&sF2[(c+j)*64 + scol]     = v0;
            *(float4*)&sF2[(c+j)*64 + scol + 4] = v1;
        }
    }
    __syncthreads();
    // layer 3: 64 pts x 256 channels, K=128 (w3 staged in 4 chunks over sW)
    int c0 = lane*4, c1 = 128 + lane*4;
    float acc[8][8];
    #pragma unroll
    for(int i=0;i<8;i++)
        #pragma unroll
        for(int j=0;j<8;j++) acc[i][j]=0.f;

    for(int kc=0;kc<128;kc+=32){
        {   // stage w3 chunk: rows kc..kc+31 (contiguous 8192 floats)
            const float4* wsrc = (const float4*)(w3 + (size_t)kc*256);
            float4* wdst = (float4*)sW;
            #pragma unroll
            for(int i=0;i<8;i++) wdst[tid + i*256] = wsrc[tid + i*256];
        }
        __syncthreads();
        #pragma unroll 4
        for(int kk=0;kk<32;kk++){
            int k = kc + kk;
            float4 wa = *(const float4*)&sW[kk*256 + c0];
            float4 wb = *(const float4*)&sW[kk*256 + c1];
            int rcol = (pg*8) ^ (((k>>2) & 7) * 8);
            float4 fa = *(const float4*)&sF2[k*64 + rcol];
            float4 fb = *(const float4*)&sF2[k*64 + rcol + 4];
            float f[8] = {fa.x,fa.y,fa.z,fa.w,fb.x,fb.y,fb.z,fb.w};
            float w[8] = {wa.x,wa.y,wa.z,wa.w,wb.x,wb.y,wb.z,wb.w};
            #pragma unroll
            for(int i=0;i<8;i++)
                #pragma unroll
                for(int j=0;j<8;j++)
                    acc[i][j] += f[i]*w[j];
        }
        __syncthreads();
    }
    // per-thread max over 8 points; +bias (max(a)+b == max(a+b))
    float m[8];
    #pragma unroll
    for(int j=0;j<8;j++){
        float mm = acc[0][j];
        #pragma unroll
        for(int i=1;i<8;i++) mm = fmaxf(mm, acc[i][j]);
        int ch = (j<4) ? (c0+j) : (c1+j-4);
        m[j] = mm + b3[ch];
    }
    #pragma unroll
    for(int j=0;j<8;j++){
        int ch = (j<4) ? (c0+j) : (c1+j-4);
        sF1[pg*256 + ch] = m[j];
    }
    __syncthreads();
    if(tid < 256){
        int ch = tid;   // 256 channels
        float mm = sF1[ch];
        #pragma unroll
        for(int g=1;g<8;g++) mm = fmaxf(mm, sF1[g*256 + ch]);
        atomicMax(&g_gfenc[b][ch], fenc(mm));   // running max across steps
    }
}

// ---------------- attention bias partials: grid (BB, 32), 128 threads ----------------
__global__ void k_attpre(const float* __restrict__ att_w1, const float* __restrict__ att_b1){
    int b = blockIdx.x, s = blockIdx.y;
    int j = threadIdx.x;
    int r0 = s*12;
    float acc = (s==0) ? att_b1[j] : 0.f;
    #pragma unroll
    for(int kk=0;kk<12;kk++){
        int r = r0 + kk;              // 0..383
        float v = (r < GD) ? fdec(g_gfenc[b][r]) : g_h[b][r-GD];
        acc += v * att_w1[(3+r)*128 + j];
    }
    g_attpart[s][b][j] = acc;
}

// ---------------- attention score: 2 points per thread, 128-thread blocks ------------
// grid ((N+255)/256, BB).
__global__ void k_attscore(const float* __restrict__ att_w1, const float* __restrict__ att_w2,
                           const float* __restrict__ att_b2, int N){
    __shared__ float  s_ab[128];
    __shared__ float4 s_pk[128];       // {w1x,w1y,w1z,w2} per hidden unit
    int b = blockIdx.y;
    int tid = threadIdx.x;
    {
        float a = 0.f;
        #pragma unroll
        for(int s=0;s<32;s++) a += g_attpart[s][b][tid];
        s_ab[tid] = a;
        s_pk[tid] = make_float4(att_w1[tid], att_w1[128+tid], att_w1[256+tid], att_w2[tid]);
    }
    __syncthreads();

    int n0 = blockIdx.x*256 + tid;
    int n1 = n0 + 128;
    bool a0 = n0 < N, a1 = n1 < N;
    float x0=0,y0=0,z0=0,x1=0,y1=0,z1=0;
    if(a0){ x0=g_canvas[b][n0][0]; y0=g_canvas[b][n0][1]; z0=g_canvas[b][n0][2]; }
    if(a1){ x1=g_canvas[b][n1][0]; y1=g_canvas[b][n1][1]; z1=g_canvas[b][n1][2]; }
    float s0 = att_b2[0], s1 = att_b2[0];
    #pragma unroll 4
    for(int jj=0;jj<128;jj++){
        float4 w = s_pk[jj];
        float ab = s_ab[jj];
        float h0 = ab + x0*w.x + y0*w.y + z0*w.z;
        float h1 = ab + x1*w.x + y1*w.y + z1*w.z;
        s0 += fmaxf(h0, 0.f) * w.w;
        s1 += fmaxf(h1, 0.f) * w.w;
    }
    if(a0) g_scores[b][n0] = s0;
    if(a1) g_scores[b][n1] = s1;
}

// ---------------- fused softmax + center + radix top-K + LSTM + ref1 ----------------
// one block per batch, 1024 threads, dynamic smem = MAXN*4 bytes for d2
__global__ void __launch_bounds__(1024)
k_center(int N,
         const float* __restrict__ wih, const float* __restrict__ whh,
         const float* __restrict__ bih, const float* __restrict__ bhh,
         const float* __restrict__ ref_w1, const float* __restrict__ ref_b1){
    extern __shared__ float sD[];
    __shared__ float rw[32];
    __shared__ int   ri[32];
    __shared__ float s4[32][4];
    __shared__ float s_bc[8];
    __shared__ unsigned s_eqn;
    __shared__ int   s_eqi[256];
    __shared__ float s_in[262];
    __shared__ float s_g[512];
    __shared__ float s_hold[HD];
    __shared__ float s_hn[HD];
    __shared__ int   s_hist[2048];
    __shared__ int   s_scan[32];
    __shared__ unsigned s_bin;
    __shared__ int   s_below;
    int b = blockIdx.x, tid = threadIdx.x;
    int lane = tid & 31, wid = tid >> 5;

    // --- max of scores ---
    float m = -FLT_MAX;
    for(int n=tid;n<N;n+=1024) m = fmaxf(m, g_scores[b][n]);
    #pragma unroll
    for(int o=16;o;o>>=1) m = fmaxf(m, __shfl_xor_sync(0xffffffffu, m, o));
    if(lane==0) rw[wid] = m;
    __syncthreads();
    if(tid==0){
        float mm = rw[0];
        for(int i=1;i<32;i++) mm = fmaxf(mm, rw[i]);
        s_bc[0] = mm;
    }
    __syncthreads();
    float mx = s_bc[0];

    // --- exp sums + weighted coordinate sums ---
    float se=0,sx=0,sy=0,sz=0;
    for(int n=tid;n<N;n+=1024){
        float e = expf(g_scores[b][n]-mx);
        se += e;
        sx += e*g_canvas[b][n][0];
        sy += e*g_canvas[b][n][1];
        sz += e*g_canvas[b][n][2];
    }
    #pragma unroll
    for(int o=16;o;o>>=1){
        se += __shfl_xor_sync(0xffffffffu, se, o);
        sx += __shfl_xor_sync(0xffffffffu, sx, o);
        sy += __shfl_xor_sync(0xffffffffu, sy, o);
        sz += __shfl_xor_sync(0xffffffffu, sz, o);
    }
    if(lane==0){ s4[wid][0]=se; s4[wid][1]=sx; s4[wid][2]=sy; s4[wid][3]=sz; }
    __syncthreads();
    if(tid==0){
        float te=0,tx=0,ty=0,tz=0;
        for(int i=0;i<32;i++){ te+=s4[i][0]; tx+=s4[i][1]; ty+=s4[i][2]; tz+=s4[i][3]; }
        float cx=tx/te, cy=ty/te, cz=tz/te;
        s_bc[1]=cx; s_bc[2]=cy; s_bc[3]=cz;
        g_center[b][0]=cx; g_center[b][1]=cy; g_center[b][2]=cz;
        s_eqn = 0;
    }
    __syncthreads();
    float cx=s_bc[1], cy=s_bc[2], cz=s_bc[3];

    // --- squared distances into smem (monotone with dist -> same top-K) ---
    for(int n=tid;n<N;n+=1024){
        float dx=g_canvas[b][n][0]-cx, dy=g_canvas[b][n][1]-cy, dz=g_canvas[b][n][2]-cz;
        sD[n] = dx*dx+dy*dy+dz*dz;
    }
    __syncthreads();

    // --- exact Kth-smallest bits via 3-pass radix (11/11/10 bits, d2 >= 0 so bit31=0)
    unsigned u;
    {
        unsigned B1, B2, B3;
        int Kp = KSEL;
        // ---- pass 1: bin = bits >> 21
        for(int i=tid;i<2048;i+=1024) s_hist[i]=0;
        __syncthreads();
        for(int n=tid;n<N;n+=1024)
            atomicAdd(&s_hist[__float_as_uint(sD[n])>>21], 1);
        __syncthreads();
        for(int pass=0; pass<3; pass++){
            // block scan: thread owns bins 2*tid, 2*tid+1
            int h0 = s_hist[2*tid], h1 = s_hist[2*tid+1];
            int s = h0 + h1, pfx = s;
            #pragma unroll
            for(int o=1;o<32;o<<=1){ int v=__shfl_up_sync(0xffffffffu,pfx,o); if(lane>=o) pfx+=v; }
            if(lane==31) s_scan[wid]=pfx;
            __syncthreads();
            if(tid==0){ int r=0; for(int i=0;i<32;i++){ int v=s_scan[i]; s_scan[i]=r; r+=v; } }
            __syncthreads();
            int before = s_scan[wid] + pfx - s;
            if(before < Kp && before + h0 >= Kp){ s_bin = 2*tid; s_below = before; }
            else if(before + h0 < Kp && before + h0 + h1 >= Kp){ s_bin = 2*tid+1; s_below = before + h0; }
            __syncthreads();
            unsigned B = s_bin;
            Kp -= s_below;
            __syncthreads();
            if(pass == 2){ B3 = B; break; }
            if(pass == 0) B1 = B; else B2 = B;
            // prepare next histogram
            for(int i=tid;i<2048;i+=1024) s_hist[i]=0;
            __syncthreads();
            if(pass == 0){
                for(int n=tid;n<N;n+=1024){
                    unsigned bits = __float_as_uint(sD[n]);
                    if((bits>>21) == B1) atomicAdd(&s_hist[(bits>>10)&0x7FF], 1);
                }
            } else {
                unsigned p2 = (B1<<11) | B2;
                for(int n=tid;n<N;n+=1024){
                    unsigned bits = __float_as_uint(sD[n]);
                    if((bits>>10) == p2) atomicAdd(&s_hist[bits & 0x3FF], 1);
                }
            }
            __syncthreads();
        }
        u = (B1<<21) | (B2<<10) | B3;
    }

    // --- sums of strictly-below + boundary ties (index order matches lax.top_k) ---
    float ax=0,ay=0,az=0; int c=0;
    for(int n=tid;n<N;n+=1024){
        unsigned bits = __float_as_uint(sD[n]);
        if(bits < u){
            c++; ax+=g_canvas[b][n][0]; ay+=g_canvas[b][n][1]; az+=g_canvas[b][n][2];
        }
        if(bits == u){
            unsigned p = atomicAdd(&s_eqn, 1u);
            if(p < 256) s_eqi[p] = n;
        }
    }
    #pragma unroll
    for(int o=16;o;o>>=1){
        c  += __shfl_xor_sync(0xffffffffu, c, o);
        ax += __shfl_xor_sync(0xffffffffu, ax, o);
        ay += __shfl_xor_sync(0xffffffffu, ay, o);
        az += __shfl_xor_sync(0xffffffffu, az, o);
    }
    if(lane==0){ ri[wid]=c; s4[wid][0]=ax; s4[wid][1]=ay; s4[wid][2]=az; }
    __syncthreads();
    if(tid==0){
        int tc=0; float tx=0,ty=0,tz=0;
        for(int i=0;i<32;i++){ tc+=ri[i]; tx+=s4[i][0]; ty+=s4[i][1]; tz+=s4[i][2]; }
        int r = KSEL - tc;                 // boundary elems needed, in index order
        int mcount = min((int)s_eqn, 256);
        for(int it=0; it<r; it++){
            int best=-1, bi=0x7fffffff;
            for(int q=0;q<mcount;q++){ int v=s_eqi[q]; if(v>=0 && v<bi){bi=v;best=q;} }
            if(best<0) break;
            s_eqi[best] = -1;
            tx += g_canvas[b][bi][0]; ty += g_canvas[b][bi][1]; tz += g_canvas[b][bi][2];
        }
        float inv = 1.f/KSEL;
        float px = tx*inv - cx, py = ty*inv - cy, pz = tz*inv - cz;
        g_patch[b][0]=px; g_patch[b][1]=py; g_patch[b][2]=pz;
        s_bc[4]=px; s_bc[5]=py; s_bc[6]=pz;
    }
    __syncthreads();

    // ===== fused LSTM gates + cell + refine layer 1 (this batch only) =====
    for(int i=tid;i<262;i+=1024){
        float v;
        if(i < GD)        v = fdec(g_gfenc[b][i]);
        else if(i < GD+3) v = s_bc[1+i-GD];
        else              v = s_bc[4+i-GD-3];
        s_in[i]=v;
    }
    for(int i=tid;i<HD;i+=1024) s_hold[i]=g_h[b][i];
    __syncthreads();
    if(tid < 512){   // gate j for this batch (same per-(b,j) accumulation order)
        int j = tid;
        float a = bih[j] + bhh[j];
        #pragma unroll 2
        for(int k=0;k<262;k++) a += s_in[k]*wih[k*512 + j];
        #pragma unroll 2
        for(int k=0;k<HD;k++)  a += s_hold[k]*whh[k*512 + j];
        s_g[j]=a;
    }
    __syncthreads();
    if(tid < HD){
        int j = tid;
        float gi=s_g[j], gf=s_g[HD+j], gg=s_g[2*HD+j], go=s_g[3*HD+j];
        float sgi=1.f/(1.f+expf(-gi)), sgf=1.f/(1.f+expf(-gf)), sgo=1.f/(1.f+expf(-go));
        float cc = sgf*g_c[b][j] + sgi*tanhf(gg);
        g_c[b][j] = cc;
        float h = sgo*tanhf(cc);
        g_h[b][j] = h;
        s_hn[j] = h;
    }
    __syncthreads();
    if(tid < HD){
        int j = tid;
        float a = ref_b1[j];
        #pragma unroll 2
        for(int k=0;k<HD;k++) a += s_hn[k]*ref_w1[k*128+j];
        g_hid[b][j] = fmaxf(a, 0.f);
    }
}

// ---------------- refine decoder layer 2 -> new canvas points ----------------
__global__ void k_ref2(const float* __restrict__ ref_w2, const float* __restrict__ ref_b2, int N){
    int o = blockIdx.x*256 + threadIdx.x;
    if(o >= BB*REFO) return;
    int b = o/REFO, q = o - b*REFO;
    float a = ref_b2[q];
    const float* h = g_hid[b];
    #pragma unroll 4
    for(int k=0;k<HD;k++) a += h[k]*ref_w2[k*REFO + q];
    int pt = q/3, d = q - 3*pt;
    g_canvas[b][N+pt][d] = a*0.02f + g_center[b][d];
}

// ---------------- chamfer: all 4 directions in one launch ----------------
#define CTI 2048
__global__ void k_cham(const float* __restrict__ gt){
    __shared__ float4 sy[CTI];
    __shared__ float red[256];
    int b = blockIdx.y, tid = threadIdx.x;
    int t = blockIdx.x;
    int dir, tb;
    if(t < 16){ dir=0; tb=t; }
    else if(t < 32){ dir=1; tb=t-16; }
    else if(t < 77){ dir=2; tb=t-32; }
    else { dir=3; tb=t-77; }

    int xsel = (dir==1 || dir==3) ? 1 : 0;           // 0=canvas, 1=gt
    int xoff = (dir==2) ? NP0 : 0;
    int ysel = 1 - xsel;
    int yoff = (dir==3) ? NP0 : 0;
    int Ny   = (dir==3) ? (MAXN-NP0) : NP0;
    int ai   = dir;

    int n = tb*256 + tid;   // all tiles are full
    float x0,x1,x2;
    if(xsel==0){
        x0=g_canvas[b][xoff+n][0]; x1=g_canvas[b][xoff+n][1]; x2=g_canvas[b][xoff+n][2];
    } else {
        const float* p = gt + ((size_t)b*NP0 + n)*3;
        x0=p[0]; x1=p[1]; x2=p[2];
    }
    float xx = x0*x0 + x1*x1 + x2*x2;
    float mn0=FLT_MAX, mn1=FLT_MAX, mn2=FLT_MAX, mn3=FLT_MAX;

    for(int t0=0;t0<Ny;t0+=CTI){
        int cnt = min(CTI, Ny-t0);
        __syncthreads();
        if(ysel==0){
            for(int i=tid;i<cnt;i+=256){
                float y0=g_canvas[b][yoff+t0+i][0], y1=g_canvas[b][yoff+t0+i][1], y2=g_canvas[b][yoff+t0+i][2];
                sy[i] = make_float4(y0,y1,y2, y0*y0+y1*y1+y2*y2);
            }
        } else {
            const float* ys = gt + ((size_t)b*NP0 + t0)*3;
            for(int i=tid;i<cnt;i+=256){
                float y0=ys[3*i], y1=ys[3*i+1], y2=ys[3*i+2];
                sy[i] = make_float4(y0,y1,y2, y0*y0+y1*y1+y2*y2);
            }
        }
        __syncthreads();
        for(int j=0;j<cnt;j+=4){
            float4 A=sy[j], B=sy[j+1], C=sy[j+2], D=sy[j+3];
            float v0 = fmaf(-2.f, fmaf(x0,A.x, fmaf(x1,A.y, x2*A.z)), A.w);
            float v1 = fmaf(-2.f, fmaf(x0,B.x, fmaf(x1,B.y, x2*B.z)), B.w);
            float v2 = fmaf(-2.f, fmaf(x0,C.x, fmaf(x1,C.y, x2*C.z)), C.w);
            float v3 = fmaf(-2.f, fmaf(x0,D.x, fmaf(x1,D.y, x2*D.z)), D.w);
            mn0 = fminf(mn0, v0);
            mn1 = fminf(mn1, v1);
            mn2 = fminf(mn2, v2);
            mn3 = fminf(mn3, v3);
        }
    }
    float mn = fminf(fminf(mn0,mn1), fminf(mn2,mn3));
    red[tid] = xx + mn;
    __syncthreads();
    for(int s=128;s>0;s>>=1){ if(tid<s) red[tid]+=red[tid+s]; __syncthreads(); }
    if(tid==0) atomicAdd(&g_acc[ai], (double)red[0]);
}

__global__ void k_final(float* __restrict__ out){
    double cd_in  = g_acc[0]/(4.0*NP0)          + g_acc[1]/(4.0*NP0);
    double cd_new = g_acc[2]/(4.0*(10.0*NEWP))  + g_acc[3]/(4.0*NP0);
    out[0] = (float)(0.1*cd_in + 1.0*cd_new);
}

// ---------------- host launch ----------------
extern "C" void kernel_launch(void* const* d_in, const int* in_sizes, int n_in,
                              void* d_out, int out_size){
    const float* points   = (const float*)d_in[0];
    const float* gt       = (const float*)d_in[1];
    const float* enc_w1   = (const float*)d_in[2];
    const float* enc_b1   = (const float*)d_in[3];
    const float* enc_w2   = (const float*)d_in[4];
    const float* enc_b2   = (const float*)d_in[5];
    const float* enc_w3   = (const float*)d_in[6];
    const float* enc_b3   = (const float*)d_in[7];
    const float* att_w1   = (const float*)d_in[8];
    const float* att_b1   = (const float*)d_in[9];
    const float* att_w2   = (const float*)d_in[10];
    const float* att_b2   = (const float*)d_in[11];
    const float* lstm_wih = (const float*)d_in[12];
    const float* lstm_whh = (const float*)d_in[13];
    const float* lstm_bih = (const float*)d_in[14];
    const float* lstm_bhh = (const float*)d_in[15];
    const float* ref_w1   = (const float*)d_in[16];
    const float* ref_b1   = (const float*)d_in[17];
    const float* ref_w2   = (const float*)d_in[18];
    const float* ref_b2   = (const float*)d_in[19];

    // opt-in dynamic smem (idempotent, capture-safe)
    cudaFuncSetAttribute(k_center, cudaFuncAttributeMaxDynamicSharedMemorySize, 64*1024);
    cudaFuncSetAttribute(k_enc,    cudaFuncAttributeMaxDynamicSharedMemorySize, 80*1024);

    k_init<<<(BB*NP0*3 + 255)/256, 256>>>(points);

    int N = NP0;
    for(int s=0;s<NSTEPS;s++){
        // Incremental encoding: canvas only grows and encoder weights are fixed,
        // so only the points appended last step need encoding; gfeat is a running max.
        int e0   = (s==0) ? 0   : (N - NEWP);
        int ecnt = (s==0) ? NP0 : NEWP;
        dim3 ge(BB, ecnt/64);
        k_enc<<<ge, 256, 80*1024>>>(enc_w1, enc_b1, enc_w2, enc_b2, enc_w3, enc_b3, e0);
        k_attpre<<<dim3(BB,32), 128>>>(att_w1, att_b1);
        k_attscore<<<dim3((N+255)/256, BB), 128>>>(att_w1, att_w2, att_b2, N);
        k_center<<<BB, 1024, MAXN*4>>>(N, lstm_wih, lstm_whh, lstm_bih, lstm_bhh, ref_w1, ref_b1);
        k_ref2<<<(BB*REFO+255)/256, 256>>>(ref_w2, ref_b2, N);
        N += NEWP;
    }

    k_cham<<<dim3(93, BB), 256>>>(gt);
    k_final<<<1,1>>>((float*)d_out);
}